// round 14
// baseline (speedup 1.0000x reference)
#include <cuda_runtime.h>
#include <cuda_fp16.h>
#include <math.h>
#include <stdint.h>

#define N_VID 36000
#define DM    512
#define NWIN  50
#define WS    720
#define SEQ   784
#define TXTL  64

// ---------------- scratch (static device allocations; no cudaMalloc) ----------------
__device__ float  g_qkv_t[TXTL * 1536];         // txt QKV (fp32)
__device__ __half g_Qw_h[NWIN * SEQ * DM];      // windowed Q (rope, fp16)
__device__ __half g_Kw_h[NWIN * SEQ * DM];
__device__ __half g_Vhi_h[NWIN * SEQ * DM];     // V (fp16)
__device__ __half g_preproj_h[N_VID * DM];      // attn out, token order (fp16)
__device__ float  g_txtacc[TXTL * DM];          // txt attn out (fp32)
__device__ __half g_vid_h[N_VID * DM];          // fp16 vid
__device__ __half g_wqkvT_h[1536 * DM];         // w_qkv_vid^T [N][K] fp16
__device__ __half g_woutT_h[DM * DM];           // w_out_vid^T [N][K] fp16
__device__ float  g_invfreq[64];                // rope inverse frequencies per d-pair

__device__ __forceinline__ int token_of(int w, int p) {
    int it = w & 1;
    int ih = (w >> 1) % 5;
    int iw = w / 10;
    int tl = p / 144;
    int rem = p % 144;
    int hl = rem >> 4;
    int wl = rem & 15;
    return ((it * 5 + tl) * 45 + (ih * 9 + hl)) * 80 + (iw * 16 + wl);
}

__device__ __forceinline__ float to_tf32(float x) {
    float r;
    asm("cvt.rna.tf32.f32 %0, %1;" : "=f"(r) : "f"(x));
    return r;
}

// tf32 mma (kept for small txt GEMMs)
__device__ __forceinline__ void mma_tf32(float* c, unsigned a0, unsigned a1,
                                         unsigned a2, unsigned a3,
                                         unsigned b0, unsigned b1) {
    asm volatile(
        "mma.sync.aligned.m16n8k8.row.col.f32.tf32.tf32.f32 "
        "{%0,%1,%2,%3}, {%4,%5,%6,%7}, {%8,%9}, {%0,%1,%2,%3};"
        : "+f"(c[0]), "+f"(c[1]), "+f"(c[2]), "+f"(c[3])
        : "r"(a0), "r"(a1), "r"(a2), "r"(a3), "r"(b0), "r"(b1));
}

// fp16 mma, fp32 accum
__device__ __forceinline__ void mma_f16(float* c, const uint32_t* a,
                                        uint32_t b0, uint32_t b1) {
    asm volatile(
        "mma.sync.aligned.m16n8k16.row.col.f32.f16.f16.f32 "
        "{%0,%1,%2,%3}, {%4,%5,%6,%7}, {%8,%9}, {%0,%1,%2,%3};"
        : "+f"(c[0]), "+f"(c[1]), "+f"(c[2]), "+f"(c[3])
        : "r"(a[0]), "r"(a[1]), "r"(a[2]), "r"(a[3]), "r"(b0), "r"(b1));
}

__device__ __forceinline__ void ldsm_x4(uint32_t* r, uint32_t addr) {
    asm volatile("ldmatrix.sync.aligned.m8n8.x4.shared.b16 {%0,%1,%2,%3}, [%4];"
                 : "=r"(r[0]), "=r"(r[1]), "=r"(r[2]), "=r"(r[3]) : "r"(addr));
}
__device__ __forceinline__ void ldsm_x4_t(uint32_t* r, uint32_t addr) {
    asm volatile("ldmatrix.sync.aligned.m8n8.x4.trans.shared.b16 {%0,%1,%2,%3}, [%4];"
                 : "=r"(r[0]), "=r"(r[1]), "=r"(r[2]), "=r"(r[3]) : "r"(addr));
}

// packed fp16x2 exp2 via MUFU
__device__ __forceinline__ uint32_t h2exp2_u(uint32_t x) {
    uint32_t r;
    asm("ex2.approx.f16x2 %0, %1;" : "=r"(r) : "r"(x));
    return r;
}

__device__ __forceinline__ uint32_t smem_u32(const void* p) {
    return (uint32_t)__cvta_generic_to_shared(p);
}

// cp.async helpers (16B; invalid -> zero-fill)
__device__ __forceinline__ void cp_async16(void* smem_dst, const void* gsrc, bool valid) {
    unsigned saddr = (unsigned)__cvta_generic_to_shared(smem_dst);
    int sz = valid ? 16 : 0;
    asm volatile("cp.async.cg.shared.global [%0], [%1], 16, %2;\n"
                 :: "r"(saddr), "l"(gsrc), "r"(sz));
}
__device__ __forceinline__ void cp_commit() {
    asm volatile("cp.async.commit_group;\n" ::);
}
template <int N>
__device__ __forceinline__ void cp_wait() {
    asm volatile("cp.async.wait_group %0;\n" :: "n"(N));
}

// ---------------- init: zero txt accumulator + rope inverse-frequency table ----------------
__global__ void init_kernel() {
    int i = blockIdx.x * 256 + threadIdx.x;
    if (i < TXTL * DM) g_txtacc[i] = 0.f;
    if (i < 64) {
        int d0 = 2 * i;
        int dl, da;
        if (d0 < 32)      { dl = d0;      da = 32; }
        else if (d0 < 80) { dl = d0 - 32; da = 48; }
        else              { dl = d0 - 80; da = 48; }
        g_invfreq[i] = powf(10000.0f, -((float)dl) / (float)da);
    }
}

// ---------------- round fp32 -> fp16, elementwise ----------------
__global__ void round_half_kernel(const float* __restrict__ src, __half* __restrict__ dst, int n4) {
    int i = blockIdx.x * 256 + threadIdx.x;
    if (i < n4) {
        float4 v = reinterpret_cast<const float4*>(src)[i];
        reinterpret_cast<__half2*>(dst)[2 * i]     = __floats2half2_rn(v.x, v.y);
        reinterpret_cast<__half2*>(dst)[2 * i + 1] = __floats2half2_rn(v.z, v.w);
    }
}

// ---------------- transpose + round weights: w[K][N] fp32 -> wt[N][K] fp16 ----------------
__global__ void transpose_round_h_kernel(const float* __restrict__ w, __half* __restrict__ wt,
                                         int K, int N) {
    __shared__ float t[32][33];
    int nb = blockIdx.x * 32, kb = blockIdx.y * 32;
    int tx = threadIdx.x, ty = threadIdx.y;   // 32 x 8
#pragma unroll
    for (int j = 0; j < 4; ++j)
        t[ty + j * 8][tx] = w[(long)(kb + ty + j * 8) * N + nb + tx];
    __syncthreads();
#pragma unroll
    for (int j = 0; j < 4; ++j)
        wt[(long)(nb + ty + j * 8) * K + kb + tx] = __float2half_rn(t[tx][ty + j * 8]);
}

// ============= fp16 tensor-core GEMM: C[M,N] = A[M,K] @ Bt[N,K]^T =============
#define GH_STRIDE 40   // halves per row (32 + 8 pad)
#define CS_STRIDE 132
#define GEMM_SMEM_BYTES (128 * CS_STRIDE * 4)   // 67584

template <bool FUSED>
__global__ void __launch_bounds__(256) h16_gemm_t(
    const __half* __restrict__ A, const __half* __restrict__ Bt, float* __restrict__ C,
    int M, int N, int K)
{
    extern __shared__ char smraw[];
    __half* smh = (__half*)smraw;
    float*  cs  = (float*)smraw;

    const int tid  = threadIdx.x;
    const int warp = tid >> 5, lane = tid & 31;
    const int g = lane >> 2, tig = lane & 3;
    const int lr = lane & 15, lk = (lane >> 4) * 8;
    const int wm = (warp & 1) * 64;
    const int wn = (warp >> 1) * 32;
    const int rowBase = blockIdx.y * 128;
    const int colBase = blockIdx.x * 128;
    const int nIter = K / 32;

    float c[4][4][4];
#pragma unroll
    for (int mt = 0; mt < 4; ++mt)
#pragma unroll
        for (int nt = 0; nt < 4; ++nt)
#pragma unroll
            for (int i = 0; i < 4; ++i) c[mt][nt][i] = 0.f;

#pragma unroll
    for (int i = 0; i < 2; ++i) {
        int idx = tid + i * 256;
        int r = idx >> 2, o = idx & 3;
        int grow = rowBase + r;
        cp_async16(&smh[r * GH_STRIDE + o * 8], &A[(long)grow * K + o * 8], grow < M);
        cp_async16(&smh[10240 + r * GH_STRIDE + o * 8], &Bt[(long)(colBase + r) * K + o * 8], true);
    }
    cp_commit();

    for (int it = 0; it < nIter; ++it) {
        int b = it & 1;
        if (it + 1 < nIter) {
            int k0 = (it + 1) * 32;
            int bn = (it + 1) & 1;
#pragma unroll
            for (int i = 0; i < 2; ++i) {
                int idx = tid + i * 256;
                int r = idx >> 2, o = idx & 3;
                int grow = rowBase + r;
                cp_async16(&smh[bn * 5120 + r * GH_STRIDE + o * 8],
                           &A[(long)grow * K + k0 + o * 8], grow < M);
                cp_async16(&smh[10240 + bn * 5120 + r * GH_STRIDE + o * 8],
                           &Bt[(long)(colBase + r) * K + k0 + o * 8], true);
            }
            cp_commit();
            cp_wait<1>();
        } else {
            cp_wait<0>();
        }
        __syncthreads();

        uint32_t aBase = smem_u32(smh) + (b * 5120 + (wm + lr) * GH_STRIDE + lk) * 2;
        uint32_t bBase = smem_u32(smh) + (10240 + b * 5120 + (wn + lr) * GH_STRIDE + lk) * 2;
#pragma unroll
        for (int s = 0; s < 2; ++s) {
            uint32_t af[4][4];
#pragma unroll
            for (int mt = 0; mt < 4; ++mt)
                ldsm_x4(af[mt], aBase + mt * (16 * GH_STRIDE * 2) + s * 32);
#pragma unroll
            for (int np = 0; np < 2; ++np) {
                uint32_t bf[4];
                ldsm_x4(bf, bBase + np * (16 * GH_STRIDE * 2) + s * 32);
#pragma unroll
                for (int mt = 0; mt < 4; ++mt) {
                    mma_f16(c[mt][np * 2],     af[mt], bf[0], bf[2]);
                    mma_f16(c[mt][np * 2 + 1], af[mt], bf[1], bf[3]);
                }
            }
        }
        __syncthreads();
    }

    // stage C tile to fp32 smem
#pragma unroll
    for (int mt = 0; mt < 4; ++mt)
#pragma unroll
        for (int nt = 0; nt < 4; ++nt) {
            int col = wn + nt * 8 + 2 * tig;
            int r0 = wm + mt * 16 + g;
            *reinterpret_cast<float2*>(&cs[r0 * CS_STRIDE + col]) =
                make_float2(c[mt][nt][0], c[mt][nt][1]);
            *reinterpret_cast<float2*>(&cs[(r0 + 8) * CS_STRIDE + col]) =
                make_float2(c[mt][nt][2], c[mt][nt][3]);
        }
    __syncthreads();

    // coalesced write pass
    const int wr = tid >> 4;
    const int c8 = (tid & 15) * 8;
    if (!FUSED) {
#pragma unroll
        for (int j = 0; j < 8; ++j) {
            int r = wr + j * 16;
            int row = rowBase + r;
            if (row >= M) break;
            float4 v0 = *reinterpret_cast<float4*>(&cs[r * CS_STRIDE + c8]);
            float4 v1 = *reinterpret_cast<float4*>(&cs[r * CS_STRIDE + c8 + 4]);
            float4* dst = reinterpret_cast<float4*>(&C[(long)row * N + colBase + c8]);
            dst[0] = v0; dst[1] = v1;
        }
    } else {
        const int section = blockIdx.x >> 2;   // 0=Q,1=K,2=V
        const int head = blockIdx.x & 3;
        float f0 = g_invfreq[(c8 >> 1) + 0], f1 = g_invfreq[(c8 >> 1) + 1];
        float f2 = g_invfreq[(c8 >> 1) + 2], f3 = g_invfreq[(c8 >> 1) + 3];
#pragma unroll
        for (int j = 0; j < 8; ++j) {
            int r = wr + j * 16;
            int token = rowBase + r;
            if (token >= M) break;
            int t = token / 3600, rem = token % 3600;
            int hh = rem / 80, ww2 = rem % 80;
            int it2 = t / 5, tl = t % 5;
            int ih = hh / 9, hl = hh % 9;
            int iw = ww2 >> 4, wl = ww2 & 15;
            int wwin = iw * 10 + ih * 2 + it2;
            int p = tl * 144 + hl * 16 + wl;
            long ob = ((long)(wwin * SEQ + p) * 4 + head) * 128 + c8;
            float4 v0 = *reinterpret_cast<float4*>(&cs[r * CS_STRIDE + c8]);
            float4 v1 = *reinterpret_cast<float4*>(&cs[r * CS_STRIDE + c8 + 4]);
            __half2 o[4];
            if (section == 2) {
                o[0] = __floats2half2_rn(v0.x, v0.y);
                o[1] = __floats2half2_rn(v0.z, v0.w);
                o[2] = __floats2half2_rn(v1.x, v1.y);
                o[3] = __floats2half2_rn(v1.z, v1.w);
                *reinterpret_cast<uint2*>(&g_Vhi_h[ob]) = *reinterpret_cast<uint2*>(&o[0]);
                *reinterpret_cast<uint2*>(&g_Vhi_h[ob + 4]) = *reinterpret_cast<uint2*>(&o[2]);
            } else {
                float pos;
                if (c8 < 32)      pos = (float)t;
                else if (c8 < 80) pos = (float)hh;
                else              pos = (float)ww2;
                float s0 = __sinf(pos * f0), c0 = __cosf(pos * f0);
                float s1 = __sinf(pos * f1), c1 = __cosf(pos * f1);
                float s2 = __sinf(pos * f2), c2 = __cosf(pos * f2);
                float s3 = __sinf(pos * f3), c3 = __cosf(pos * f3);
                o[0] = __floats2half2_rn(v0.x * c0 - v0.y * s0, v0.y * c0 + v0.x * s0);
                o[1] = __floats2half2_rn(v0.z * c1 - v0.w * s1, v0.w * c1 + v0.z * s1);
                o[2] = __floats2half2_rn(v1.x * c2 - v1.y * s2, v1.y * c2 + v1.x * s2);
                o[3] = __floats2half2_rn(v1.z * c3 - v1.w * s3, v1.w * c3 + v1.z * s3);
                __half* base = (section == 0) ? g_Qw_h : g_Kw_h;
                *reinterpret_cast<uint2*>(&base[ob]) = *reinterpret_cast<uint2*>(&o[0]);
                *reinterpret_cast<uint2*>(&base[ob + 4]) = *reinterpret_cast<uint2*>(&o[2]);
            }
        }
    }
}

// ---------------- old tf32 GEMM — small txt GEMMs only ----------------
#define SA_STRIDE 36
#define SB_STRIDE 136
__global__ void __launch_bounds__(256) tf32_gemm_kernel(
    const float* __restrict__ A, const float* __restrict__ B, float* __restrict__ C,
    int M, int N, int K, float alpha)
{
    __shared__ float sA[128 * SA_STRIDE];
    __shared__ float sB[32 * SB_STRIDE];

    const int tid  = threadIdx.x;
    const int warp = tid >> 5, lane = tid & 31;
    const int g = lane >> 2, tig = lane & 3;
    const int wm = (warp & 1) * 64;
    const int wn = (warp >> 1) * 32;
    const int rowBase = blockIdx.y * 128;
    const int colBase = blockIdx.x * 128;

    float c[4][4][4];
#pragma unroll
    for (int mt = 0; mt < 4; ++mt)
#pragma unroll
        for (int nt = 0; nt < 4; ++nt)
#pragma unroll
            for (int i = 0; i < 4; ++i) c[mt][nt][i] = 0.f;

    float4 pa[4], pb[4];
#pragma unroll
    for (int i = 0; i < 4; ++i) {
        int idx = tid + i * 256;
        int r = idx >> 3, c4 = idx & 7;
        int grow = rowBase + r;
        pa[i] = (grow < M) ? *reinterpret_cast<const float4*>(&A[(long)grow * K + c4 * 4])
                           : make_float4(0.f, 0.f, 0.f, 0.f);
        int rb = idx >> 5, cb4 = idx & 31;
        pb[i] = *reinterpret_cast<const float4*>(&B[(long)rb * N + colBase + cb4 * 4]);
    }

    const int nIter = K / 32;
    for (int it = 0; it < nIter; ++it) {
#pragma unroll
        for (int i = 0; i < 4; ++i) {
            int idx = tid + i * 256;
            int r = idx >> 3, c4 = idx & 7;
            float* d = &sA[r * SA_STRIDE + c4 * 4];
            d[0] = to_tf32(pa[i].x); d[1] = to_tf32(pa[i].y);
            d[2] = to_tf32(pa[i].z); d[3] = to_tf32(pa[i].w);
            int rb = idx >> 5, cb4 = idx & 31;
            float* db = &sB[rb * SB_STRIDE + cb4 * 4];
            db[0] = to_tf32(pb[i].x); db[1] = to_tf32(pb[i].y);
            db[2] = to_tf32(pb[i].z); db[3] = to_tf32(pb[i].w);
        }
        __syncthreads();

        if (it + 1 < nIter) {
            int k0 = (it + 1) * 32;
#pragma unroll
            for (int i = 0; i < 4; ++i) {
                int idx = tid + i * 256;
                int r = idx >> 3, c4 = idx & 7;
                int grow = rowBase + r;
                pa[i] = (grow < M) ? *reinterpret_cast<const float4*>(&A[(long)grow * K + k0 + c4 * 4])
                                   : make_float4(0.f, 0.f, 0.f, 0.f);
                int rb = idx >> 5, cb4 = idx & 31;
                pb[i] = *reinterpret_cast<const float4*>(&B[(long)(k0 + rb) * N + colBase + cb4 * 4]);
            }
        }

#pragma unroll
        for (int kk = 0; kk < 4; ++kk) {
            unsigned int af[4][4], bf[4][2];
#pragma unroll
            for (int mt = 0; mt < 4; ++mt) {
                int r0 = wm + mt * 16 + g;
                af[mt][0] = __float_as_uint(sA[r0 * SA_STRIDE + kk * 8 + tig]);
                af[mt][1] = __float_as_uint(sA[(r0 + 8) * SA_STRIDE + kk * 8 + tig]);
                af[mt][2] = __float_as_uint(sA[r0 * SA_STRIDE + kk * 8 + tig + 4]);
                af[mt][3] = __float_as_uint(sA[(r0 + 8) * SA_STRIDE + kk * 8 + tig + 4]);
            }
#pragma unroll
            for (int nt = 0; nt < 4; ++nt) {
                int cn = wn + nt * 8 + g;
                bf[nt][0] = __float_as_uint(sB[(kk * 8 + tig) * SB_STRIDE + cn]);
                bf[nt][1] = __float_as_uint(sB[(kk * 8 + tig + 4) * SB_STRIDE + cn]);
            }
#pragma unroll
            for (int mt = 0; mt < 4; ++mt)
#pragma unroll
                for (int nt = 0; nt < 4; ++nt)
                    mma_tf32(c[mt][nt], af[mt][0], af[mt][1], af[mt][2], af[mt][3],
                             bf[nt][0], bf[nt][1]);
        }
        __syncthreads();
    }

#pragma unroll
    for (int mt = 0; mt < 4; ++mt) {
#pragma unroll
        for (int nt = 0; nt < 4; ++nt) {
            int row0 = rowBase + wm + mt * 16 + g;
            int col = colBase + wn + nt * 8 + 2 * tig;
            if (row0 < M) {
                float2 o = make_float2(c[mt][nt][0] * alpha, c[mt][nt][1] * alpha);
                *reinterpret_cast<float2*>(&C[(long)row0 * N + col]) = o;
            }
            int row1 = row0 + 8;
            if (row1 < M) {
                float2 o = make_float2(c[mt][nt][2] * alpha, c[mt][nt][3] * alpha);
                *reinterpret_cast<float2*>(&C[(long)row1 * N + col]) = o;
            }
        }
    }
}

// ---------------- broadcast txt qkv rows into all windows (no rope) ----------------
__global__ void __launch_bounds__(256) txt_broadcast_kernel() {
    int w = blockIdx.x, tr = blockIdx.y;
    int tid = threadIdx.x;
    int h = tid >> 6, pr = tid & 63;
    int d0 = pr * 2;
    const float* base = &g_qkv_t[(long)tr * 1536 + h * 128];
    float q0 = base[d0],        q1 = base[d0 + 1];
    float k0 = base[512 + d0],  k1 = base[512 + d0 + 1];
    float v0 = base[1024 + d0], v1 = base[1024 + d0 + 1];
    long ob = ((long)(w * SEQ + WS + tr) * 4 + h) * 128 + d0;
    *reinterpret_cast<__half2*>(&g_Qw_h[ob])  = __floats2half2_rn(q0, q1);
    *reinterpret_cast<__half2*>(&g_Kw_h[ob])  = __floats2half2_rn(k0, k1);
    *reinterpret_cast<__half2*>(&g_Vhi_h[ob]) = __floats2half2_rn(v0, v1);
}

// ---------------- fp16 flash attention: QT=128, KT=64, tail-skip guards ----------------
#define QT2   128
#define KT2   64
#define PADDH 136
#define PSTR  72
#define NKT   13
#define SMEM_K0   17408
#define SMEM_KBUF 9216
#define SMEM_V    35840
#define ATTN3_SMEM_BYTES 90112

__global__ void __launch_bounds__(256) attn3_kernel() {
    extern __shared__ char smraw[];
    __half* sh = (__half*)smraw;
    float* sPart = (float*)(smraw + 89088);
    const uint32_t sbase = smem_u32(sh);

    const float NEGINF = __int_as_float(0xff800000);
    const float scale = 0.08838834764831843f;
    const float SL = 0.12751089f;
    const uint32_t ONES2 = 0x3C003C00u;

    int qt = blockIdx.x, h = blockIdx.y, w = blockIdx.z;
    int tid = threadIdx.x;
    const int warp = tid >> 5, lane = tid & 31;
    const int g = lane >> 2, tig = lane & 3;
    const int lr = lane & 15, lk = (lane >> 4) * 8;
    const int wm = (warp & 3) * 32;
    const int ng = warp >> 2;
    const int wn1 = ng * 32;
    const int wn2 = ng * 64;

    const long gbase = ((long)(w * SEQ) * 4 + h) * 128;
    const int qrow0 = qt * QT2;
    const bool mActive = (qrow0 + wm) < SEQ;   // this warp's 32-row m-group has valid rows

    // prologue: Q + K0, one commit group
#pragma unroll
    for (int i = 0; i < 8; ++i) {
        int idx = tid + i * 256;
        int r = idx >> 4, o = idx & 15;
        cp_async16(&sh[r * PADDH + o * 8],
                   &g_Qw_h[gbase + (long)(qrow0 + r) * 512 + o * 8], qrow0 + r < SEQ);
    }
#pragma unroll
    for (int i = 0; i < 4; ++i) {
        int idx = tid + i * 256;
        int r = idx >> 4, o = idx & 15;
        cp_async16(&sh[SMEM_K0 + r * PADDH + o * 8],
                   &g_Kw_h[gbase + (long)r * 512 + o * 8], r < SEQ);
    }
    cp_commit();

    float oacc[2][8][4];
#pragma unroll
    for (int mt = 0; mt < 2; ++mt)
#pragma unroll
        for (int nf = 0; nf < 8; ++nf)
#pragma unroll
            for (int i = 0; i < 4; ++i) oacc[mt][nf][i] = 0.f;

    float lex[2][4];
#pragma unroll
    for (int mt = 0; mt < 2; ++mt)
#pragma unroll
        for (int i = 0; i < 4; ++i) lex[mt][i] = 0.f;

    float mOld[2][2];
#pragma unroll
    for (int mt = 0; mt < 2; ++mt)
#pragma unroll
        for (int hf = 0; hf < 2; ++hf) mOld[mt][hf] = NEGINF;

    for (int kt = 0; kt < NKT; ++kt) {
        const int b = kt & 1;
        const int kbase = kt * KT2;
        __half* sKb = sh + SMEM_K0 + b * SMEM_KBUF;
        __half* sP  = sKb;

        __syncthreads();

        {
#pragma unroll
            for (int i = 0; i < 4; ++i) {
                int idx = tid + i * 256;
                int r = idx >> 4, o = idx & 15;
                cp_async16(&sh[SMEM_V + r * PADDH + o * 8],
                           &g_Vhi_h[gbase + (long)(kbase + r) * 512 + o * 8], kbase + r < SEQ);
            }
            cp_commit();
        }
        if (kt + 1 < NKT) {
            int kb = (kt + 1) * KT2;
            __half* sKn = sh + SMEM_K0 + ((kt + 1) & 1) * SMEM_KBUF;
#pragma unroll
            for (int i = 0; i < 4; ++i) {
                int idx = tid + i * 256;
                int r = idx >> 4, o = idx & 15;
                cp_async16(&sKn[r * PADDH + o * 8],
                           &g_Kw_h[gbase + (long)(kb + r) * 512 + o * 8], kb + r < SEQ);
            }
            cp_commit();
            cp_wait<2>();
        } else {
            cp_wait<1>();
        }
        __syncthreads();

        // ---- phase 1: S = Q @ K^T (skip if m-group invalid; skip invalid col-groups) ----
        float sacc[2][4][4];
#pragma unroll
        for (int mt = 0; mt < 2; ++mt)
#pragma unroll
            for (int nf = 0; nf < 4; ++nf)
#pragma unroll
                for (int i = 0; i < 4; ++i) sacc[mt][nf][i] = 0.f;

        float aF[2][2];
        if (mActive) {
            const bool npv0 = (kbase + wn1) < SEQ;
            const bool npv1 = (kbase + wn1 + 16) < SEQ;
            uint32_t qa0 = sbase + ((wm + lr) * PADDH + lk) * 2;
            uint32_t ka0 = smem_u32(sKb) + ((wn1 + lr) * PADDH + lk) * 2;
#pragma unroll
            for (int kk = 0; kk < 8; ++kk) {
                uint32_t aQ[2][4];
#pragma unroll
                for (int mt = 0; mt < 2; ++mt)
                    ldsm_x4(aQ[mt], qa0 + mt * (16 * PADDH * 2) + kk * 32);
#pragma unroll
                for (int np = 0; np < 2; ++np) {
                    if (np == 0 ? !npv0 : !npv1) continue;
                    uint32_t bK[4];
                    ldsm_x4(bK, ka0 + np * (16 * PADDH * 2) + kk * 32);
#pragma unroll
                    for (int mt = 0; mt < 2; ++mt) {
                        mma_f16(sacc[mt][np * 2],     aQ[mt], bK[0], bK[2]);
                        mma_f16(sacc[mt][np * 2 + 1], aQ[mt], bK[1], bK[3]);
                    }
                }
            }

            // ---- mask + partial row max ----
            bool cval[4][2];
#pragma unroll
            for (int nf = 0; nf < 4; ++nf) {
                int c0 = kbase + wn1 + nf * 8 + 2 * tig;
                cval[nf][0] = (c0 < SEQ);
                cval[nf][1] = (c0 + 1 < SEQ);
            }
            float mp[2][2];
#pragma unroll
            for (int mt = 0; mt < 2; ++mt)
#pragma unroll
                for (int hf = 0; hf < 2; ++hf) {
                    float m = NEGINF;
#pragma unroll
                    for (int nf = 0; nf < 4; ++nf)
#pragma unroll
                        for (int pr = 0; pr < 2; ++pr) {
                            float s = cval[nf][pr] ? sacc[mt][nf][hf * 2 + pr] : NEGINF;
                            sacc[mt][nf][hf * 2 + pr] = s;
                            m = fmaxf(m, s);
                        }
                    m = fmaxf(m, __shfl_xor_sync(0xffffffffu, m, 1));
                    m = fmaxf(m, __shfl_xor_sync(0xffffffffu, m, 2));
                    mp[mt][hf] = m;
                }
            if (tig == 0) {
#pragma unroll
                for (int mt = 0; mt < 2; ++mt)
#pragma unroll
                    for (int hf = 0; hf < 2; ++hf)
                        sPart[(wm + mt * 16 + g + hf * 8) * 2 + ng] = mp[mt][hf];
            }
        }
        __syncthreads();

        // ---- exp2.f16x2 + P(half) write ----
        if (mActive) {
#pragma unroll
            for (int mt = 0; mt < 2; ++mt)
#pragma unroll
                for (int hf = 0; hf < 2; ++hf) {
                    int row = wm + mt * 16 + g + hf * 8;
                    float mn = fmaxf(mOld[mt][hf], fmaxf(sPart[row * 2], sPart[row * 2 + 1]));
                    aF[mt][hf] = __expf((mOld[mt][hf] - mn) * scale);
                    mOld[mt][hf] = mn;
                }
#pragma unroll
            for (int mt = 0; mt < 2; ++mt)
#pragma unroll
                for (int hf = 0; hf < 2; ++hf) {
                    int row = wm + mt * 16 + g + hf * 8;
                    float mnSL = mOld[mt][hf] * SL;
#pragma unroll
                    for (int nf = 0; nf < 4; ++nf) {
                        float a0 = fmaf(sacc[mt][nf][hf * 2],     SL, -mnSL);
                        float a1 = fmaf(sacc[mt][nf][hf * 2 + 1], SL, -mnSL);
                        __half2 ha = __floats2half2_rn(a0, a1);
                        uint32_t p2 = h2exp2_u(*reinterpret_cast<uint32_t*>(&ha));
                        int col = wn1 + nf * 8 + 2 * tig;
                        *reinterpret_cast<uint32_t*>(&sP[row * PSTR + col]) = p2;
                    }
                }
        }
        if (kt + 1 < NKT) cp_wait<1>(); else cp_wait<0>();
        __syncthreads();

        if (mActive) {
            // ---- rescale O and l ----
#pragma unroll
            for (int mt = 0; mt < 2; ++mt) {
#pragma unroll
                for (int nf = 0; nf < 8; ++nf) {
                    oacc[mt][nf][0] *= aF[mt][0]; oacc[mt][nf][1] *= aF[mt][0];
                    oacc[mt][nf][2] *= aF[mt][1]; oacc[mt][nf][3] *= aF[mt][1];
                }
                lex[mt][0] *= aF[mt][0]; lex[mt][1] *= aF[mt][0];
                lex[mt][2] *= aF[mt][1]; lex[mt][3] *= aF[mt][1];
            }

            // ---- phase 2: O += P @ V (+ l += P @ ones); skip all-zero P k-chunks ----
            uint32_t pa0 = smem_u32(sP) + ((wm + lr) * PSTR + lk) * 2;
            int vkr = ((lane >> 3) & 1) * 8 + (lane & 7);
            int vnc = (lane >> 4) * 8;
            uint32_t va0 = sbase + (SMEM_V + vkr * PADDH + wn2 + vnc) * 2;
#pragma unroll
            for (int kk2 = 0; kk2 < 4; ++kk2) {
                if (kbase + kk2 * 16 >= SEQ) break;   // P cols all exactly zero beyond SEQ
                uint32_t aP[2][4];
#pragma unroll
                for (int mt = 0; mt < 2; ++mt) {
                    ldsm_x4(aP[mt], pa0 + mt * (16 * PSTR * 2) + kk2 * 32);
                    mma_f16(lex[mt], aP[mt], ONES2, ONES2);
                }
#pragma unroll
                for (int ng2 = 0; ng2 < 4; ++ng2) {
                    uint32_t bh[4];
                    ldsm_x4_t(bh, va0 + kk2 * (16 * PADDH * 2) + ng2 * 32);
#pragma unroll
                    for (int mt = 0; mt < 2; ++mt) {
                        mma_f16(oacc[mt][ng2 * 2],     aP[mt], bh[0], bh[1]);
                        mma_f16(oacc[mt][ng2 * 2 + 1], aP[mt], bh[2], bh[3]);
                    }
                }
            }
        }
    }

    // epilogue: txt rows via atomics; vid rows staged into sQ (dead) for coalesced scatter
#pragma unroll
    for (int mt = 0; mt < 2; ++mt)
#pragma unroll
        for (int hf = 0; hf < 2; ++hf) {
            int ql = wm + mt * 16 + g + hf * 8;
            int qg = qrow0 + ql;
            if (qg >= SEQ) continue;
            float inv = 1.f / lex[mt][hf * 2];
            if (qg >= WS) {
                int tr = qg - WS;
                float* dst = &g_txtacc[(long)tr * DM + h * 128];
#pragma unroll
                for (int nf = 0; nf < 8; ++nf) {
                    int col = wn2 + nf * 8 + 2 * tig;
                    atomicAdd(&dst[col],     oacc[mt][nf][hf * 2] * inv);
                    atomicAdd(&dst[col + 1], oacc[mt][nf][hf * 2 + 1] * inv);
                }
            } else {
#pragma unroll
                for (int nf = 0; nf < 8; ++nf) {
                    int col = wn2 + nf * 8 + 2 * tig;
                    *reinterpret_cast<__half2*>(&sh[ql * PADDH + col]) =
                        __floats2half2_rn(oacc[mt][nf][hf * 2] * inv,
                                          oacc[mt][nf][hf * 2 + 1] * inv);
                }
            }
        }
    __syncthreads();

    // coalesced scatter: 16 threads/row x 16B (uint4 = 8 halves), vid rows only
    {
        int wr = tid >> 4, c8 = (tid & 15) * 8;
#pragma unroll
        for (int j = 0; j < 8; ++j) {
            int ql = wr + j * 16;
            int qg = qrow0 + ql;
            if (qg >= WS) break;
            int token = token_of(w, qg);
            uint4 v = *reinterpret_cast<uint4*>(&sh[ql * PADDH + c8]);
            *reinterpret_cast<uint4*>(&g_preproj_h[(long)token * DM + h * 128 + c8]) = v;
        }
    }
}

// ---------------- launch ----------------
extern "C" void kernel_launch(void* const* d_in, const int* in_sizes, int n_in,
                              void* d_out, int out_size) {
    const float* vid       = (const float*)d_in[0];
    const float* txt       = (const float*)d_in[1];
    const float* w_qkv_vid = (const float*)d_in[2];
    const float* w_qkv_txt = (const float*)d_in[3];
    const float* w_out_vid = (const float*)d_in[4];
    const float* w_out_txt = (const float*)d_in[5];
    float* out = (float*)d_out;

    cudaFuncSetAttribute(attn3_kernel, cudaFuncAttributeMaxDynamicSharedMemorySize,
                         ATTN3_SMEM_BYTES);
    cudaFuncSetAttribute(h16_gemm_t<true>, cudaFuncAttributeMaxDynamicSharedMemorySize,
                         GEMM_SMEM_BYTES);
    cudaFuncSetAttribute(h16_gemm_t<false>, cudaFuncAttributeMaxDynamicSharedMemorySize,
                         GEMM_SMEM_BYTES);

    float *p_qkv_t, *p_txt;
    __half *p_pre_h, *p_vid_h, *p_wqkvT_h, *p_woutT_h;
    cudaGetSymbolAddress((void**)&p_qkv_t,   g_qkv_t);
    cudaGetSymbolAddress((void**)&p_txt,     g_txtacc);
    cudaGetSymbolAddress((void**)&p_pre_h,   g_preproj_h);
    cudaGetSymbolAddress((void**)&p_vid_h,   g_vid_h);
    cudaGetSymbolAddress((void**)&p_wqkvT_h, g_wqkvT_h);
    cudaGetSymbolAddress((void**)&p_woutT_h, g_woutT_h);

    init_kernel<<<(TXTL * DM + 255) / 256, 256>>>();

    // fp16 conversions
    round_half_kernel<<<(N_VID * DM / 4 + 255) / 256, 256>>>(vid, p_vid_h, N_VID * DM / 4);
    transpose_round_h_kernel<<<dim3(1536 / 32, DM / 32), dim3(32, 8)>>>(w_qkv_vid, p_wqkvT_h, DM, 1536);
    transpose_round_h_kernel<<<dim3(DM / 32, DM / 32), dim3(32, 8)>>>(w_out_vid, p_woutT_h, DM, DM);

    // txt QKV (fp32), then broadcast into windows
    tf32_gemm_kernel<<<dim3(1536 / 128, 1), 256>>>(
        txt, w_qkv_txt, p_qkv_t, TXTL, 1536, DM, 1.f);

    // vid QKV projection with fused rope + window scatter (coalesced)
    h16_gemm_t<true><<<dim3(1536 / 128, (N_VID + 127) / 128), 256, GEMM_SMEM_BYTES>>>(
        p_vid_h, p_wqkvT_h, (float*)nullptr, N_VID, 1536, DM);

    txt_broadcast_kernel<<<dim3(NWIN, TXTL), 256>>>();

    // attention (fp16, tail-skip)
    attn3_kernel<<<dim3(7, 4, NWIN), 256, ATTN3_SMEM_BYTES>>>();

    // output projections
    h16_gemm_t<false><<<dim3(DM / 128, (N_VID + 127) / 128), 256, GEMM_SMEM_BYTES>>>(
        p_pre_h, p_woutT_h, out, N_VID, DM, DM);
    tf32_gemm_kernel<<<dim3(DM / 128, 1), 256>>>(
        p_txt, w_out_txt, out + (long)N_VID * DM, TXTL, DM, DM, 1.f / 50.f);
}

// round 15
// speedup vs baseline: 1.0909x; 1.0909x over previous
#include <cuda_runtime.h>
#include <cuda_fp16.h>
#include <math.h>
#include <stdint.h>

#define N_VID 36000
#define DM    512
#define NWIN  50
#define WS    720
#define SEQ   784
#define TXTL  64

// ---------------- scratch (static device allocations; no cudaMalloc) ----------------
__device__ float  g_qkv_t[TXTL * 1536];         // txt QKV (fp32)
__device__ __half g_Qw_h[NWIN * SEQ * DM];      // windowed Q (rope, fp16)
__device__ __half g_Kw_h[NWIN * SEQ * DM];
__device__ __half g_Vhi_h[NWIN * SEQ * DM];     // V (fp16)
__device__ __half g_preproj_h[N_VID * DM];      // attn out, token order (fp16)
__device__ float  g_txtacc[TXTL * DM];          // txt attn out (fp32)
__device__ __half g_vid_h[N_VID * DM];          // fp16 vid
__device__ __half g_wqkvT_h[1536 * DM];         // w_qkv_vid^T [N][K] fp16
__device__ __half g_woutT_h[DM * DM];           // w_out_vid^T [N][K] fp16
__device__ float  g_invfreq[64];                // rope inverse frequencies per d-pair

__device__ __forceinline__ int token_of(int w, int p) {
    int it = w & 1;
    int ih = (w >> 1) % 5;
    int iw = w / 10;
    int tl = p / 144;
    int rem = p % 144;
    int hl = rem >> 4;
    int wl = rem & 15;
    return ((it * 5 + tl) * 45 + (ih * 9 + hl)) * 80 + (iw * 16 + wl);
}

__device__ __forceinline__ float to_tf32(float x) {
    float r;
    asm("cvt.rna.tf32.f32 %0, %1;" : "=f"(r) : "f"(x));
    return r;
}

// tf32 mma (kept for small txt GEMMs)
__device__ __forceinline__ void mma_tf32(float* c, unsigned a0, unsigned a1,
                                         unsigned a2, unsigned a3,
                                         unsigned b0, unsigned b1) {
    asm volatile(
        "mma.sync.aligned.m16n8k8.row.col.f32.tf32.tf32.f32 "
        "{%0,%1,%2,%3}, {%4,%5,%6,%7}, {%8,%9}, {%0,%1,%2,%3};"
        : "+f"(c[0]), "+f"(c[1]), "+f"(c[2]), "+f"(c[3])
        : "r"(a0), "r"(a1), "r"(a2), "r"(a3), "r"(b0), "r"(b1));
}

// fp16 mma, fp32 accum
__device__ __forceinline__ void mma_f16(float* c, const uint32_t* a,
                                        uint32_t b0, uint32_t b1) {
    asm volatile(
        "mma.sync.aligned.m16n8k16.row.col.f32.f16.f16.f32 "
        "{%0,%1,%2,%3}, {%4,%5,%6,%7}, {%8,%9}, {%0,%1,%2,%3};"
        : "+f"(c[0]), "+f"(c[1]), "+f"(c[2]), "+f"(c[3])
        : "r"(a[0]), "r"(a[1]), "r"(a[2]), "r"(a[3]), "r"(b0), "r"(b1));
}

__device__ __forceinline__ void ldsm_x4(uint32_t* r, uint32_t addr) {
    asm volatile("ldmatrix.sync.aligned.m8n8.x4.shared.b16 {%0,%1,%2,%3}, [%4];"
                 : "=r"(r[0]), "=r"(r[1]), "=r"(r[2]), "=r"(r[3]) : "r"(addr));
}
__device__ __forceinline__ void ldsm_x4_t(uint32_t* r, uint32_t addr) {
    asm volatile("ldmatrix.sync.aligned.m8n8.x4.trans.shared.b16 {%0,%1,%2,%3}, [%4];"
                 : "=r"(r[0]), "=r"(r[1]), "=r"(r[2]), "=r"(r[3]) : "r"(addr));
}

// packed fp16x2 exp2 via MUFU
__device__ __forceinline__ uint32_t h2exp2_u(uint32_t x) {
    uint32_t r;
    asm("ex2.approx.f16x2 %0, %1;" : "=r"(r) : "r"(x));
    return r;
}

__device__ __forceinline__ uint32_t smem_u32(const void* p) {
    return (uint32_t)__cvta_generic_to_shared(p);
}

// cp.async helpers (16B; invalid -> zero-fill)
__device__ __forceinline__ void cp_async16(void* smem_dst, const void* gsrc, bool valid) {
    unsigned saddr = (unsigned)__cvta_generic_to_shared(smem_dst);
    int sz = valid ? 16 : 0;
    asm volatile("cp.async.cg.shared.global [%0], [%1], 16, %2;\n"
                 :: "r"(saddr), "l"(gsrc), "r"(sz));
}
__device__ __forceinline__ void cp_commit() {
    asm volatile("cp.async.commit_group;\n" ::);
}
template <int N>
__device__ __forceinline__ void cp_wait() {
    asm volatile("cp.async.wait_group %0;\n" :: "n"(N));
}

// ---------------- init: zero txt accumulator + rope inverse-frequency table ----------------
__global__ void init_kernel() {
    int i = blockIdx.x * 256 + threadIdx.x;
    if (i < TXTL * DM) g_txtacc[i] = 0.f;
    if (i < 64) {
        int d0 = 2 * i;
        int dl, da;
        if (d0 < 32)      { dl = d0;      da = 32; }
        else if (d0 < 80) { dl = d0 - 32; da = 48; }
        else              { dl = d0 - 80; da = 48; }
        g_invfreq[i] = powf(10000.0f, -((float)dl) / (float)da);
    }
}

// ---------------- round fp32 -> fp16, elementwise ----------------
__global__ void round_half_kernel(const float* __restrict__ src, __half* __restrict__ dst, int n4) {
    int i = blockIdx.x * 256 + threadIdx.x;
    if (i < n4) {
        float4 v = reinterpret_cast<const float4*>(src)[i];
        reinterpret_cast<__half2*>(dst)[2 * i]     = __floats2half2_rn(v.x, v.y);
        reinterpret_cast<__half2*>(dst)[2 * i + 1] = __floats2half2_rn(v.z, v.w);
    }
}

// ---------------- transpose + round weights: w[K][N] fp32 -> wt[N][K] fp16 ----------------
__global__ void transpose_round_h_kernel(const float* __restrict__ w, __half* __restrict__ wt,
                                         int K, int N) {
    __shared__ float t[32][33];
    int nb = blockIdx.x * 32, kb = blockIdx.y * 32;
    int tx = threadIdx.x, ty = threadIdx.y;   // 32 x 8
#pragma unroll
    for (int j = 0; j < 4; ++j)
        t[ty + j * 8][tx] = w[(long)(kb + ty + j * 8) * N + nb + tx];
    __syncthreads();
#pragma unroll
    for (int j = 0; j < 4; ++j)
        wt[(long)(nb + ty + j * 8) * K + kb + tx] = __float2half_rn(t[tx][ty + j * 8]);
}

// ============= fp16 tensor-core GEMM: C[M,N] = A[M,K] @ Bt[N,K]^T =============
#define GH_STRIDE 40   // halves per row (32 + 8 pad)
#define CS_STRIDE 132
#define GEMM_SMEM_BYTES (128 * CS_STRIDE * 4)   // 67584

template <bool FUSED>
__global__ void __launch_bounds__(256) h16_gemm_t(
    const __half* __restrict__ A, const __half* __restrict__ Bt, float* __restrict__ C,
    int M, int N, int K)
{
    extern __shared__ char smraw[];
    __half* smh = (__half*)smraw;
    float*  cs  = (float*)smraw;

    const int tid  = threadIdx.x;
    const int warp = tid >> 5, lane = tid & 31;
    const int g = lane >> 2, tig = lane & 3;
    const int lr = lane & 15, lk = (lane >> 4) * 8;
    const int wm = (warp & 1) * 64;
    const int wn = (warp >> 1) * 32;
    const int rowBase = blockIdx.y * 128;
    const int colBase = blockIdx.x * 128;
    const int nIter = K / 32;

    float c[4][4][4];
#pragma unroll
    for (int mt = 0; mt < 4; ++mt)
#pragma unroll
        for (int nt = 0; nt < 4; ++nt)
#pragma unroll
            for (int i = 0; i < 4; ++i) c[mt][nt][i] = 0.f;

#pragma unroll
    for (int i = 0; i < 2; ++i) {
        int idx = tid + i * 256;
        int r = idx >> 2, o = idx & 3;
        int grow = rowBase + r;
        cp_async16(&smh[r * GH_STRIDE + o * 8], &A[(long)grow * K + o * 8], grow < M);
        cp_async16(&smh[10240 + r * GH_STRIDE + o * 8], &Bt[(long)(colBase + r) * K + o * 8], true);
    }
    cp_commit();

    for (int it = 0; it < nIter; ++it) {
        int b = it & 1;
        if (it + 1 < nIter) {
            int k0 = (it + 1) * 32;
            int bn = (it + 1) & 1;
#pragma unroll
            for (int i = 0; i < 2; ++i) {
                int idx = tid + i * 256;
                int r = idx >> 2, o = idx & 3;
                int grow = rowBase + r;
                cp_async16(&smh[bn * 5120 + r * GH_STRIDE + o * 8],
                           &A[(long)grow * K + k0 + o * 8], grow < M);
                cp_async16(&smh[10240 + bn * 5120 + r * GH_STRIDE + o * 8],
                           &Bt[(long)(colBase + r) * K + k0 + o * 8], true);
            }
            cp_commit();
            cp_wait<1>();
        } else {
            cp_wait<0>();
        }
        __syncthreads();

        uint32_t aBase = smem_u32(smh) + (b * 5120 + (wm + lr) * GH_STRIDE + lk) * 2;
        uint32_t bBase = smem_u32(smh) + (10240 + b * 5120 + (wn + lr) * GH_STRIDE + lk) * 2;
#pragma unroll
        for (int s = 0; s < 2; ++s) {
            uint32_t af[4][4];
#pragma unroll
            for (int mt = 0; mt < 4; ++mt)
                ldsm_x4(af[mt], aBase + mt * (16 * GH_STRIDE * 2) + s * 32);
#pragma unroll
            for (int np = 0; np < 2; ++np) {
                uint32_t bf[4];
                ldsm_x4(bf, bBase + np * (16 * GH_STRIDE * 2) + s * 32);
#pragma unroll
                for (int mt = 0; mt < 4; ++mt) {
                    mma_f16(c[mt][np * 2],     af[mt], bf[0], bf[2]);
                    mma_f16(c[mt][np * 2 + 1], af[mt], bf[1], bf[3]);
                }
            }
        }
        __syncthreads();
    }

    // stage C tile to fp32 smem
#pragma unroll
    for (int mt = 0; mt < 4; ++mt)
#pragma unroll
        for (int nt = 0; nt < 4; ++nt) {
            int col = wn + nt * 8 + 2 * tig;
            int r0 = wm + mt * 16 + g;
            *reinterpret_cast<float2*>(&cs[r0 * CS_STRIDE + col]) =
                make_float2(c[mt][nt][0], c[mt][nt][1]);
            *reinterpret_cast<float2*>(&cs[(r0 + 8) * CS_STRIDE + col]) =
                make_float2(c[mt][nt][2], c[mt][nt][3]);
        }
    __syncthreads();

    // coalesced write pass
    const int wr = tid >> 4;
    const int c8 = (tid & 15) * 8;
    if (!FUSED) {
#pragma unroll
        for (int j = 0; j < 8; ++j) {
            int r = wr + j * 16;
            int row = rowBase + r;
            if (row >= M) break;
            float4 v0 = *reinterpret_cast<float4*>(&cs[r * CS_STRIDE + c8]);
            float4 v1 = *reinterpret_cast<float4*>(&cs[r * CS_STRIDE + c8 + 4]);
            float4* dst = reinterpret_cast<float4*>(&C[(long)row * N + colBase + c8]);
            dst[0] = v0; dst[1] = v1;
        }
    } else {
        const int section = blockIdx.x >> 2;   // 0=Q,1=K,2=V
        const int head = blockIdx.x & 3;
        float f0 = g_invfreq[(c8 >> 1) + 0], f1 = g_invfreq[(c8 >> 1) + 1];
        float f2 = g_invfreq[(c8 >> 1) + 2], f3 = g_invfreq[(c8 >> 1) + 3];
#pragma unroll
        for (int j = 0; j < 8; ++j) {
            int r = wr + j * 16;
            int token = rowBase + r;
            if (token >= M) break;
            int t = token / 3600, rem = token % 3600;
            int hh = rem / 80, ww2 = rem % 80;
            int it2 = t / 5, tl = t % 5;
            int ih = hh / 9, hl = hh % 9;
            int iw = ww2 >> 4, wl = ww2 & 15;
            int wwin = iw * 10 + ih * 2 + it2;
            int p = tl * 144 + hl * 16 + wl;
            long ob = ((long)(wwin * SEQ + p) * 4 + head) * 128 + c8;
            float4 v0 = *reinterpret_cast<float4*>(&cs[r * CS_STRIDE + c8]);
            float4 v1 = *reinterpret_cast<float4*>(&cs[r * CS_STRIDE + c8 + 4]);
            __half2 o[4];
            if (section == 2) {
                o[0] = __floats2half2_rn(v0.x, v0.y);
                o[1] = __floats2half2_rn(v0.z, v0.w);
                o[2] = __floats2half2_rn(v1.x, v1.y);
                o[3] = __floats2half2_rn(v1.z, v1.w);
                *reinterpret_cast<uint2*>(&g_Vhi_h[ob]) = *reinterpret_cast<uint2*>(&o[0]);
                *reinterpret_cast<uint2*>(&g_Vhi_h[ob + 4]) = *reinterpret_cast<uint2*>(&o[2]);
            } else {
                float pos;
                if (c8 < 32)      pos = (float)t;
                else if (c8 < 80) pos = (float)hh;
                else              pos = (float)ww2;
                float s0 = __sinf(pos * f0), c0 = __cosf(pos * f0);
                float s1 = __sinf(pos * f1), c1 = __cosf(pos * f1);
                float s2 = __sinf(pos * f2), c2 = __cosf(pos * f2);
                float s3 = __sinf(pos * f3), c3 = __cosf(pos * f3);
                o[0] = __floats2half2_rn(v0.x * c0 - v0.y * s0, v0.y * c0 + v0.x * s0);
                o[1] = __floats2half2_rn(v0.z * c1 - v0.w * s1, v0.w * c1 + v0.z * s1);
                o[2] = __floats2half2_rn(v1.x * c2 - v1.y * s2, v1.y * c2 + v1.x * s2);
                o[3] = __floats2half2_rn(v1.z * c3 - v1.w * s3, v1.w * c3 + v1.z * s3);
                __half* base = (section == 0) ? g_Qw_h : g_Kw_h;
                *reinterpret_cast<uint2*>(&base[ob]) = *reinterpret_cast<uint2*>(&o[0]);
                *reinterpret_cast<uint2*>(&base[ob + 4]) = *reinterpret_cast<uint2*>(&o[2]);
            }
        }
    }
}

// ---------------- old tf32 GEMM — small txt GEMMs only ----------------
#define SA_STRIDE 36
#define SB_STRIDE 136
__global__ void __launch_bounds__(256) tf32_gemm_kernel(
    const float* __restrict__ A, const float* __restrict__ B, float* __restrict__ C,
    int M, int N, int K, float alpha)
{
    __shared__ float sA[128 * SA_STRIDE];
    __shared__ float sB[32 * SB_STRIDE];

    const int tid  = threadIdx.x;
    const int warp = tid >> 5, lane = tid & 31;
    const int g = lane >> 2, tig = lane & 3;
    const int wm = (warp & 1) * 64;
    const int wn = (warp >> 1) * 32;
    const int rowBase = blockIdx.y * 128;
    const int colBase = blockIdx.x * 128;

    float c[4][4][4];
#pragma unroll
    for (int mt = 0; mt < 4; ++mt)
#pragma unroll
        for (int nt = 0; nt < 4; ++nt)
#pragma unroll
            for (int i = 0; i < 4; ++i) c[mt][nt][i] = 0.f;

    float4 pa[4], pb[4];
#pragma unroll
    for (int i = 0; i < 4; ++i) {
        int idx = tid + i * 256;
        int r = idx >> 3, c4 = idx & 7;
        int grow = rowBase + r;
        pa[i] = (grow < M) ? *reinterpret_cast<const float4*>(&A[(long)grow * K + c4 * 4])
                           : make_float4(0.f, 0.f, 0.f, 0.f);
        int rb = idx >> 5, cb4 = idx & 31;
        pb[i] = *reinterpret_cast<const float4*>(&B[(long)rb * N + colBase + cb4 * 4]);
    }

    const int nIter = K / 32;
    for (int it = 0; it < nIter; ++it) {
#pragma unroll
        for (int i = 0; i < 4; ++i) {
            int idx = tid + i * 256;
            int r = idx >> 3, c4 = idx & 7;
            float* d = &sA[r * SA_STRIDE + c4 * 4];
            d[0] = to_tf32(pa[i].x); d[1] = to_tf32(pa[i].y);
            d[2] = to_tf32(pa[i].z); d[3] = to_tf32(pa[i].w);
            int rb = idx >> 5, cb4 = idx & 31;
            float* db = &sB[rb * SB_STRIDE + cb4 * 4];
            db[0] = to_tf32(pb[i].x); db[1] = to_tf32(pb[i].y);
            db[2] = to_tf32(pb[i].z); db[3] = to_tf32(pb[i].w);
        }
        __syncthreads();

        if (it + 1 < nIter) {
            int k0 = (it + 1) * 32;
#pragma unroll
            for (int i = 0; i < 4; ++i) {
                int idx = tid + i * 256;
                int r = idx >> 3, c4 = idx & 7;
                int grow = rowBase + r;
                pa[i] = (grow < M) ? *reinterpret_cast<const float4*>(&A[(long)grow * K + k0 + c4 * 4])
                                   : make_float4(0.f, 0.f, 0.f, 0.f);
                int rb = idx >> 5, cb4 = idx & 31;
                pb[i] = *reinterpret_cast<const float4*>(&B[(long)(k0 + rb) * N + colBase + cb4 * 4]);
            }
        }

#pragma unroll
        for (int kk = 0; kk < 4; ++kk) {
            unsigned int af[4][4], bf[4][2];
#pragma unroll
            for (int mt = 0; mt < 4; ++mt) {
                int r0 = wm + mt * 16 + g;
                af[mt][0] = __float_as_uint(sA[r0 * SA_STRIDE + kk * 8 + tig]);
                af[mt][1] = __float_as_uint(sA[(r0 + 8) * SA_STRIDE + kk * 8 + tig]);
                af[mt][2] = __float_as_uint(sA[r0 * SA_STRIDE + kk * 8 + tig + 4]);
                af[mt][3] = __float_as_uint(sA[(r0 + 8) * SA_STRIDE + kk * 8 + tig + 4]);
            }
#pragma unroll
            for (int nt = 0; nt < 4; ++nt) {
                int cn = wn + nt * 8 + g;
                bf[nt][0] = __float_as_uint(sB[(kk * 8 + tig) * SB_STRIDE + cn]);
                bf[nt][1] = __float_as_uint(sB[(kk * 8 + tig + 4) * SB_STRIDE + cn]);
            }
#pragma unroll
            for (int mt = 0; mt < 4; ++mt)
#pragma unroll
                for (int nt = 0; nt < 4; ++nt)
                    mma_tf32(c[mt][nt], af[mt][0], af[mt][1], af[mt][2], af[mt][3],
                             bf[nt][0], bf[nt][1]);
        }
        __syncthreads();
    }

#pragma unroll
    for (int mt = 0; mt < 4; ++mt) {
#pragma unroll
        for (int nt = 0; nt < 4; ++nt) {
            int row0 = rowBase + wm + mt * 16 + g;
            int col = colBase + wn + nt * 8 + 2 * tig;
            if (row0 < M) {
                float2 o = make_float2(c[mt][nt][0] * alpha, c[mt][nt][1] * alpha);
                *reinterpret_cast<float2*>(&C[(long)row0 * N + col]) = o;
            }
            int row1 = row0 + 8;
            if (row1 < M) {
                float2 o = make_float2(c[mt][nt][2] * alpha, c[mt][nt][3] * alpha);
                *reinterpret_cast<float2*>(&C[(long)row1 * N + col]) = o;
            }
        }
    }
}

// ---------------- broadcast txt qkv rows into all windows (no rope) ----------------
__global__ void __launch_bounds__(256) txt_broadcast_kernel() {
    int w = blockIdx.x, tr = blockIdx.y;
    int tid = threadIdx.x;
    int h = tid >> 6, pr = tid & 63;
    int d0 = pr * 2;
    const float* base = &g_qkv_t[(long)tr * 1536 + h * 128];
    float q0 = base[d0],        q1 = base[d0 + 1];
    float k0 = base[512 + d0],  k1 = base[512 + d0 + 1];
    float v0 = base[1024 + d0], v1 = base[1024 + d0 + 1];
    long ob = ((long)(w * SEQ + WS + tr) * 4 + h) * 128 + d0;
    *reinterpret_cast<__half2*>(&g_Qw_h[ob])  = __floats2half2_rn(q0, q1);
    *reinterpret_cast<__half2*>(&g_Kw_h[ob])  = __floats2half2_rn(k0, k1);
    *reinterpret_cast<__half2*>(&g_Vhi_h[ob]) = __floats2half2_rn(v0, v1);
}

// ---------------- fp16 flash attention: QT=128, KT=64; branch-free main loop + kt=12 peel ----
#define QT2   128
#define KT2   64
#define PADDH 136
#define PSTR  72
#define NKT   13
#define SMEM_K0   17408
#define SMEM_KBUF 9216
#define SMEM_V    35840
#define ATTN3_SMEM_BYTES 90112

__global__ void __launch_bounds__(256) attn3_kernel() {
    extern __shared__ char smraw[];
    __half* sh = (__half*)smraw;
    float* sPart = (float*)(smraw + 89088);
    const uint32_t sbase = smem_u32(sh);

    const float NEGINF = __int_as_float(0xff800000);
    const float scale = 0.08838834764831843f;
    const float SL = 0.12751089f;
    const uint32_t ONES2 = 0x3C003C00u;

    int qt = blockIdx.x, h = blockIdx.y, w = blockIdx.z;
    int tid = threadIdx.x;
    const int warp = tid >> 5, lane = tid & 31;
    const int g = lane >> 2, tig = lane & 3;
    const int lr = lane & 15, lk = (lane >> 4) * 8;
    const int wm = (warp & 3) * 32;
    const int ng = warp >> 2;
    const int wn1 = ng * 32;
    const int wn2 = ng * 64;

    const long gbase = ((long)(w * SEQ) * 4 + h) * 128;
    const int qrow0 = qt * QT2;

    // prologue: Q + K0, one commit group
#pragma unroll
    for (int i = 0; i < 8; ++i) {
        int idx = tid + i * 256;
        int r = idx >> 4, o = idx & 15;
        cp_async16(&sh[r * PADDH + o * 8],
                   &g_Qw_h[gbase + (long)(qrow0 + r) * 512 + o * 8], qrow0 + r < SEQ);
    }
#pragma unroll
    for (int i = 0; i < 4; ++i) {
        int idx = tid + i * 256;
        int r = idx >> 4, o = idx & 15;
        cp_async16(&sh[SMEM_K0 + r * PADDH + o * 8],
                   &g_Kw_h[gbase + (long)r * 512 + o * 8], r < SEQ);
    }
    cp_commit();

    float oacc[2][8][4];
#pragma unroll
    for (int mt = 0; mt < 2; ++mt)
#pragma unroll
        for (int nf = 0; nf < 8; ++nf)
#pragma unroll
            for (int i = 0; i < 4; ++i) oacc[mt][nf][i] = 0.f;

    float lex[2][4];
#pragma unroll
    for (int mt = 0; mt < 2; ++mt)
#pragma unroll
        for (int i = 0; i < 4; ++i) lex[mt][i] = 0.f;

    float mOld[2][2];
#pragma unroll
    for (int mt = 0; mt < 2; ++mt)
#pragma unroll
        for (int hf = 0; hf < 2; ++hf) mOld[mt][hf] = NEGINF;

    // ================= main loop: kt = 0..11, branch-free =================
    for (int kt = 0; kt < NKT - 1; ++kt) {
        const int b = kt & 1;
        const int kbase = kt * KT2;
        __half* sKb = sh + SMEM_K0 + b * SMEM_KBUF;
        __half* sP  = sKb;

        __syncthreads();

        {
#pragma unroll
            for (int i = 0; i < 4; ++i) {
                int idx = tid + i * 256;
                int r = idx >> 4, o = idx & 15;
                cp_async16(&sh[SMEM_V + r * PADDH + o * 8],
                           &g_Vhi_h[gbase + (long)(kbase + r) * 512 + o * 8], kbase + r < SEQ);
            }
            cp_commit();
        }
        {
            int kb = kbase + KT2;
            __half* sKn = sh + SMEM_K0 + ((kt + 1) & 1) * SMEM_KBUF;
#pragma unroll
            for (int i = 0; i < 4; ++i) {
                int idx = tid + i * 256;
                int r = idx >> 4, o = idx & 15;
                cp_async16(&sKn[r * PADDH + o * 8],
                           &g_Kw_h[gbase + (long)(kb + r) * 512 + o * 8], kb + r < SEQ);
            }
            cp_commit();
            cp_wait<2>();
        }
        __syncthreads();

        // ---- phase 1: S = Q @ K^T ----
        float sacc[2][4][4];
#pragma unroll
        for (int mt = 0; mt < 2; ++mt)
#pragma unroll
            for (int nf = 0; nf < 4; ++nf)
#pragma unroll
                for (int i = 0; i < 4; ++i) sacc[mt][nf][i] = 0.f;

        {
            uint32_t qa0 = sbase + ((wm + lr) * PADDH + lk) * 2;
            uint32_t ka0 = smem_u32(sKb) + ((wn1 + lr) * PADDH + lk) * 2;
#pragma unroll
            for (int kk = 0; kk < 8; ++kk) {
                uint32_t aQ[2][4];
#pragma unroll
                for (int mt = 0; mt < 2; ++mt)
                    ldsm_x4(aQ[mt], qa0 + mt * (16 * PADDH * 2) + kk * 32);
#pragma unroll
                for (int np = 0; np < 2; ++np) {
                    uint32_t bK[4];
                    ldsm_x4(bK, ka0 + np * (16 * PADDH * 2) + kk * 32);
#pragma unroll
                    for (int mt = 0; mt < 2; ++mt) {
                        mma_f16(sacc[mt][np * 2],     aQ[mt], bK[0], bK[2]);
                        mma_f16(sacc[mt][np * 2 + 1], aQ[mt], bK[1], bK[3]);
                    }
                }
            }
        }

        // ---- row max (all cols valid for kt < 12 except none — kbase+63 <= 767 < 784) ----
        float mp[2][2];
#pragma unroll
        for (int mt = 0; mt < 2; ++mt)
#pragma unroll
            for (int hf = 0; hf < 2; ++hf) {
                float m = NEGINF;
#pragma unroll
                for (int nf = 0; nf < 4; ++nf)
#pragma unroll
                    for (int pr = 0; pr < 2; ++pr)
                        m = fmaxf(m, sacc[mt][nf][hf * 2 + pr]);
                m = fmaxf(m, __shfl_xor_sync(0xffffffffu, m, 1));
                m = fmaxf(m, __shfl_xor_sync(0xffffffffu, m, 2));
                mp[mt][hf] = m;
            }
        if (tig == 0) {
#pragma unroll
            for (int mt = 0; mt < 2; ++mt)
#pragma unroll
                for (int hf = 0; hf < 2; ++hf)
                    sPart[(wm + mt * 16 + g + hf * 8) * 2 + ng] = mp[mt][hf];
        }
        __syncthreads();

        // ---- exp2.f16x2 + P(half) write ----
        float aF[2][2];
#pragma unroll
        for (int mt = 0; mt < 2; ++mt)
#pragma unroll
            for (int hf = 0; hf < 2; ++hf) {
                int row = wm + mt * 16 + g + hf * 8;
                float mn = fmaxf(mOld[mt][hf], fmaxf(sPart[row * 2], sPart[row * 2 + 1]));
                aF[mt][hf] = __expf((mOld[mt][hf] - mn) * scale);
                mOld[mt][hf] = mn;
            }
#pragma unroll
        for (int mt = 0; mt < 2; ++mt)
#pragma unroll
            for (int hf = 0; hf < 2; ++hf) {
                int row = wm + mt * 16 + g + hf * 8;
                float mnSL = mOld[mt][hf] * SL;
#pragma unroll
                for (int nf = 0; nf < 4; ++nf) {
                    float a0 = fmaf(sacc[mt][nf][hf * 2],     SL, -mnSL);
                    float a1 = fmaf(sacc[mt][nf][hf * 2 + 1], SL, -mnSL);
                    __half2 ha = __floats2half2_rn(a0, a1);
                    uint32_t p2 = h2exp2_u(*reinterpret_cast<uint32_t*>(&ha));
                    int col = wn1 + nf * 8 + 2 * tig;
                    *reinterpret_cast<uint32_t*>(&sP[row * PSTR + col]) = p2;
                }
            }
        cp_wait<1>();
        __syncthreads();

        // ---- rescale O and l ----
#pragma unroll
        for (int mt = 0; mt < 2; ++mt) {
#pragma unroll
            for (int nf = 0; nf < 8; ++nf) {
                oacc[mt][nf][0] *= aF[mt][0]; oacc[mt][nf][1] *= aF[mt][0];
                oacc[mt][nf][2] *= aF[mt][1]; oacc[mt][nf][3] *= aF[mt][1];
            }
            lex[mt][0] *= aF[mt][0]; lex[mt][1] *= aF[mt][0];
            lex[mt][2] *= aF[mt][1]; lex[mt][3] *= aF[mt][1];
        }

        // ---- phase 2: O += P @ V (+ l += P @ ones) ----
        {
            uint32_t pa0 = smem_u32(sP) + ((wm + lr) * PSTR + lk) * 2;
            int vkr = ((lane >> 3) & 1) * 8 + (lane & 7);
            int vnc = (lane >> 4) * 8;
            uint32_t va0 = sbase + (SMEM_V + vkr * PADDH + wn2 + vnc) * 2;
#pragma unroll
            for (int kk2 = 0; kk2 < 4; ++kk2) {
                uint32_t aP[2][4];
#pragma unroll
                for (int mt = 0; mt < 2; ++mt) {
                    ldsm_x4(aP[mt], pa0 + mt * (16 * PSTR * 2) + kk2 * 32);
                    mma_f16(lex[mt], aP[mt], ONES2, ONES2);
                }
#pragma unroll
                for (int ng2 = 0; ng2 < 4; ++ng2) {
                    uint32_t bh[4];
                    ldsm_x4_t(bh, va0 + kk2 * (16 * PADDH * 2) + ng2 * 32);
#pragma unroll
                    for (int mt = 0; mt < 2; ++mt) {
                        mma_f16(oacc[mt][ng2 * 2],     aP[mt], bh[0], bh[1]);
                        mma_f16(oacc[mt][ng2 * 2 + 1], aP[mt], bh[2], bh[3]);
                    }
                }
            }
        }
    }

    // ================= peeled kt = 12 (kbase=768; 16 valid cols) =================
    {
        __half* sKb = sh + SMEM_K0;      // (12 & 1) == 0
        __half* sP  = sKb;

        __syncthreads();
        // issue V[12] (rows >= 16 zero-filled)
#pragma unroll
        for (int i = 0; i < 4; ++i) {
            int idx = tid + i * 256;
            int r = idx >> 4, o = idx & 15;
            cp_async16(&sh[SMEM_V + r * PADDH + o * 8],
                       &g_Vhi_h[gbase + (long)(768 + r) * 512 + o * 8], 768 + r < SEQ);
        }
        cp_commit();
        cp_wait<1>();    // K[12] complete (issued at kt=11)
        __syncthreads();

        float sacc[2][2][4];   // np=0 only: cols 768..783, ALL valid (no masking)
        if (ng == 0) {
#pragma unroll
            for (int mt = 0; mt < 2; ++mt)
#pragma unroll
                for (int nf = 0; nf < 2; ++nf)
#pragma unroll
                    for (int i = 0; i < 4; ++i) sacc[mt][nf][i] = 0.f;
            uint32_t qa0 = sbase + ((wm + lr) * PADDH + lk) * 2;
            uint32_t ka0 = smem_u32(sKb) + (lr * PADDH + lk) * 2;
#pragma unroll
            for (int kk = 0; kk < 8; ++kk) {
                uint32_t aQ[2][4];
#pragma unroll
                for (int mt = 0; mt < 2; ++mt)
                    ldsm_x4(aQ[mt], qa0 + mt * (16 * PADDH * 2) + kk * 32);
                uint32_t bK[4];
                ldsm_x4(bK, ka0 + kk * 32);
#pragma unroll
                for (int mt = 0; mt < 2; ++mt) {
                    mma_f16(sacc[mt][0], aQ[mt], bK[0], bK[2]);
                    mma_f16(sacc[mt][1], aQ[mt], bK[1], bK[3]);
                }
            }
            if (tig == 0) { /* nothing here; max below needs full quad */ }
            // row max over the 16 valid cols
#pragma unroll
            for (int mt = 0; mt < 2; ++mt)
#pragma unroll
                for (int hf = 0; hf < 2; ++hf) {
                    float m = fmaxf(fmaxf(sacc[mt][0][hf * 2], sacc[mt][0][hf * 2 + 1]),
                                    fmaxf(sacc[mt][1][hf * 2], sacc[mt][1][hf * 2 + 1]));
                    m = fmaxf(m, __shfl_xor_sync(0xffffffffu, m, 1));
                    m = fmaxf(m, __shfl_xor_sync(0xffffffffu, m, 2));
                    if (tig == 0)
                        sPart[(wm + mt * 16 + g + hf * 8) * 2] = m;
                }
        } else {
            if (tig == 0) {
#pragma unroll
                for (int mt = 0; mt < 2; ++mt)
#pragma unroll
                    for (int hf = 0; hf < 2; ++hf)
                        sPart[(wm + mt * 16 + g + hf * 8) * 2 + 1] = NEGINF;
            }
        }
        __syncthreads();

        float aF[2][2];
#pragma unroll
        for (int mt = 0; mt < 2; ++mt)
#pragma unroll
            for (int hf = 0; hf < 2; ++hf) {
                int row = wm + mt * 16 + g + hf * 8;
                float mn = fmaxf(mOld[mt][hf], fmaxf(sPart[row * 2], sPart[row * 2 + 1]));
                aF[mt][hf] = __expf((mOld[mt][hf] - mn) * scale);
                mOld[mt][hf] = mn;
            }
        if (ng == 0) {
#pragma unroll
            for (int mt = 0; mt < 2; ++mt)
#pragma unroll
                for (int hf = 0; hf < 2; ++hf) {
                    int row = wm + mt * 16 + g + hf * 8;
                    float mnSL = mOld[mt][hf] * SL;
#pragma unroll
                    for (int nf = 0; nf < 2; ++nf) {
                        float a0 = fmaf(sacc[mt][nf][hf * 2],     SL, -mnSL);
                        float a1 = fmaf(sacc[mt][nf][hf * 2 + 1], SL, -mnSL);
                        __half2 ha = __floats2half2_rn(a0, a1);
                        uint32_t p2 = h2exp2_u(*reinterpret_cast<uint32_t*>(&ha));
                        int col = nf * 8 + 2 * tig;
                        *reinterpret_cast<uint32_t*>(&sP[row * PSTR + col]) = p2;
                    }
                }
        }
        cp_wait<0>();
        __syncthreads();

#pragma unroll
        for (int mt = 0; mt < 2; ++mt) {
#pragma unroll
            for (int nf = 0; nf < 8; ++nf) {
                oacc[mt][nf][0] *= aF[mt][0]; oacc[mt][nf][1] *= aF[mt][0];
                oacc[mt][nf][2] *= aF[mt][1]; oacc[mt][nf][3] *= aF[mt][1];
            }
            lex[mt][0] *= aF[mt][0]; lex[mt][1] *= aF[mt][0];
            lex[mt][2] *= aF[mt][1]; lex[mt][3] *= aF[mt][1];
        }

        // phase 2: kk2 = 0 only (P cols 16..63 are exactly zero)
        {
            uint32_t pa0 = smem_u32(sP) + ((wm + lr) * PSTR + lk) * 2;
            int vkr = ((lane >> 3) & 1) * 8 + (lane & 7);
            int vnc = (lane >> 4) * 8;
            uint32_t va0 = sbase + (SMEM_V + vkr * PADDH + wn2 + vnc) * 2;
            uint32_t aP[2][4];
#pragma unroll
            for (int mt = 0; mt < 2; ++mt) {
                ldsm_x4(aP[mt], pa0 + mt * (16 * PSTR * 2));
                mma_f16(lex[mt], aP[mt], ONES2, ONES2);
            }
#pragma unroll
            for (int ng2 = 0; ng2 < 4; ++ng2) {
                uint32_t bh[4];
                ldsm_x4_t(bh, va0 + ng2 * 32);
#pragma unroll
                for (int mt = 0; mt < 2; ++mt) {
                    mma_f16(oacc[mt][ng2 * 2],     aP[mt], bh[0], bh[1]);
                    mma_f16(oacc[mt][ng2 * 2 + 1], aP[mt], bh[2], bh[3]);
                }
            }
        }
    }

    // epilogue: txt rows via atomics; vid rows staged into sQ (dead) for coalesced scatter
#pragma unroll
    for (int mt = 0; mt < 2; ++mt)
#pragma unroll
        for (int hf = 0; hf < 2; ++hf) {
            int ql = wm + mt * 16 + g + hf * 8;
            int qg = qrow0 + ql;
            if (qg >= SEQ) continue;
            float inv = 1.f / lex[mt][hf * 2];
            if (qg >= WS) {
                int tr = qg - WS;
                float* dst = &g_txtacc[(long)tr * DM + h * 128];
#pragma unroll
                for (int nf = 0; nf < 8; ++nf) {
                    int col = wn2 + nf * 8 + 2 * tig;
                    atomicAdd(&dst[col],     oacc[mt][nf][hf * 2] * inv);
                    atomicAdd(&dst[col + 1], oacc[mt][nf][hf * 2 + 1] * inv);
                }
            } else {
#pragma unroll
                for (int nf = 0; nf < 8; ++nf) {
                    int col = wn2 + nf * 8 + 2 * tig;
                    *reinterpret_cast<__half2*>(&sh[ql * PADDH + col]) =
                        __floats2half2_rn(oacc[mt][nf][hf * 2] * inv,
                                          oacc[mt][nf][hf * 2 + 1] * inv);
                }
            }
        }
    __syncthreads();

    // coalesced scatter: 16 threads/row x 16B (uint4 = 8 halves), vid rows only
    {
        int wr = tid >> 4, c8 = (tid & 15) * 8;
#pragma unroll
        for (int j = 0; j < 8; ++j) {
            int ql = wr + j * 16;
            int qg = qrow0 + ql;
            if (qg >= WS) break;
            int token = token_of(w, qg);
            uint4 v = *reinterpret_cast<uint4*>(&sh[ql * PADDH + c8]);
            *reinterpret_cast<uint4*>(&g_preproj_h[(long)token * DM + h * 128 + c8]) = v;
        }
    }
}

// ---------------- launch ----------------
extern "C" void kernel_launch(void* const* d_in, const int* in_sizes, int n_in,
                              void* d_out, int out_size) {
    const float* vid       = (const float*)d_in[0];
    const float* txt       = (const float*)d_in[1];
    const float* w_qkv_vid = (const float*)d_in[2];
    const float* w_qkv_txt = (const float*)d_in[3];
    const float* w_out_vid = (const float*)d_in[4];
    const float* w_out_txt = (const float*)d_in[5];
    float* out = (float*)d_out;

    cudaFuncSetAttribute(attn3_kernel, cudaFuncAttributeMaxDynamicSharedMemorySize,
                         ATTN3_SMEM_BYTES);
    cudaFuncSetAttribute(h16_gemm_t<true>, cudaFuncAttributeMaxDynamicSharedMemorySize,
                         GEMM_SMEM_BYTES);
    cudaFuncSetAttribute(h16_gemm_t<false>, cudaFuncAttributeMaxDynamicSharedMemorySize,
                         GEMM_SMEM_BYTES);

    float *p_qkv_t, *p_txt;
    __half *p_pre_h, *p_vid_h, *p_wqkvT_h, *p_woutT_h;
    cudaGetSymbolAddress((void**)&p_qkv_t,   g_qkv_t);
    cudaGetSymbolAddress((void**)&p_txt,     g_txtacc);
    cudaGetSymbolAddress((void**)&p_pre_h,   g_preproj_h);
    cudaGetSymbolAddress((void**)&p_vid_h,   g_vid_h);
    cudaGetSymbolAddress((void**)&p_wqkvT_h, g_wqkvT_h);
    cudaGetSymbolAddress((void**)&p_woutT_h, g_woutT_h);

    init_kernel<<<(TXTL * DM + 255) / 256, 256>>>();

    // fp16 conversions
    round_half_kernel<<<(N_VID * DM / 4 + 255) / 256, 256>>>(vid, p_vid_h, N_VID * DM / 4);
    transpose_round_h_kernel<<<dim3(1536 / 32, DM / 32), dim3(32, 8)>>>(w_qkv_vid, p_wqkvT_h, DM, 1536);
    transpose_round_h_kernel<<<dim3(DM / 32, DM / 32), dim3(32, 8)>>>(w_out_vid, p_woutT_h, DM, DM);

    // txt QKV (fp32), then broadcast into windows
    tf32_gemm_kernel<<<dim3(1536 / 128, 1), 256>>>(
        txt, w_qkv_txt, p_qkv_t, TXTL, 1536, DM, 1.f);

    // vid QKV projection with fused rope + window scatter (coalesced)
    h16_gemm_t<true><<<dim3(1536 / 128, (N_VID + 127) / 128), 256, GEMM_SMEM_BYTES>>>(
        p_vid_h, p_wqkvT_h, (float*)nullptr, N_VID, 1536, DM);

    txt_broadcast_kernel<<<dim3(NWIN, TXTL), 256>>>();

    // attention (fp16; peeled tail)
    attn3_kernel<<<dim3(7, 4, NWIN), 256, ATTN3_SMEM_BYTES>>>();

    // output projections
    h16_gemm_t<false><<<dim3(DM / 128, (N_VID + 127) / 128), 256, GEMM_SMEM_BYTES>>>(
        p_pre_h, p_woutT_h, out, N_VID, DM, DM);
    tf32_gemm_kernel<<<dim3(DM / 128, 1), 256>>>(
        p_txt, w_out_txt, out + (long)N_VID * DM, TXTL, DM, DM, 1.f / 50.f);
}

// round 17
// speedup vs baseline: 1.1329x; 1.0385x over previous
#include <cuda_runtime.h>
#include <cuda_fp16.h>
#include <math.h>
#include <stdint.h>

#define N_VID 36000
#define DM    512
#define NWIN  50
#define WS    720
#define SEQ   784
#define TXTL  64

// ---------------- scratch (static device allocations; no cudaMalloc) ----------------
__device__ float  g_qkv_t[TXTL * 1536];         // txt QKV (fp32)
__device__ __half g_Qw_h[NWIN * SEQ * DM];      // windowed Q (rope, fp16)
__device__ __half g_Kw_h[NWIN * SEQ * DM];
__device__ __half g_Vhi_h[NWIN * SEQ * DM];     // V (fp16)
__device__ __half g_preproj_h[N_VID * DM];      // attn out, token order (fp16)
__device__ float  g_txtacc[TXTL * DM];          // txt attn out (fp32)
__device__ __half g_vid_h[N_VID * DM];          // fp16 vid
__device__ __half g_wqkvT_h[1536 * DM];         // w_qkv_vid^T [N][K] fp16
__device__ __half g_woutT_h[DM * DM];           // w_out_vid^T [N][K] fp16
__device__ float  g_invfreq[64];                // rope inverse frequencies per d-pair

__device__ __forceinline__ int token_of(int w, int p) {
    int it = w & 1;
    int ih = (w >> 1) % 5;
    int iw = w / 10;
    int tl = p / 144;
    int rem = p % 144;
    int hl = rem >> 4;
    int wl = rem & 15;
    return ((it * 5 + tl) * 45 + (ih * 9 + hl)) * 80 + (iw * 16 + wl);
}

__device__ __forceinline__ float to_tf32(float x) {
    float r;
    asm("cvt.rna.tf32.f32 %0, %1;" : "=f"(r) : "f"(x));
    return r;
}

// tf32 mma (kept for small txt GEMMs)
__device__ __forceinline__ void mma_tf32(float* c, unsigned a0, unsigned a1,
                                         unsigned a2, unsigned a3,
                                         unsigned b0, unsigned b1) {
    asm volatile(
        "mma.sync.aligned.m16n8k8.row.col.f32.tf32.tf32.f32 "
        "{%0,%1,%2,%3}, {%4,%5,%6,%7}, {%8,%9}, {%0,%1,%2,%3};"
        : "+f"(c[0]), "+f"(c[1]), "+f"(c[2]), "+f"(c[3])
        : "r"(a0), "r"(a1), "r"(a2), "r"(a3), "r"(b0), "r"(b1));
}

// fp16 mma, fp32 accum
__device__ __forceinline__ void mma_f16(float* c, const uint32_t* a,
                                        uint32_t b0, uint32_t b1) {
    asm volatile(
        "mma.sync.aligned.m16n8k16.row.col.f32.f16.f16.f32 "
        "{%0,%1,%2,%3}, {%4,%5,%6,%7}, {%8,%9}, {%0,%1,%2,%3};"
        : "+f"(c[0]), "+f"(c[1]), "+f"(c[2]), "+f"(c[3])
        : "r"(a[0]), "r"(a[1]), "r"(a[2]), "r"(a[3]), "r"(b0), "r"(b1));
}

__device__ __forceinline__ void ldsm_x4(uint32_t* r, uint32_t addr) {
    asm volatile("ldmatrix.sync.aligned.m8n8.x4.shared.b16 {%0,%1,%2,%3}, [%4];"
                 : "=r"(r[0]), "=r"(r[1]), "=r"(r[2]), "=r"(r[3]) : "r"(addr));
}
__device__ __forceinline__ void ldsm_x4_t(uint32_t* r, uint32_t addr) {
    asm volatile("ldmatrix.sync.aligned.m8n8.x4.trans.shared.b16 {%0,%1,%2,%3}, [%4];"
                 : "=r"(r[0]), "=r"(r[1]), "=r"(r[2]), "=r"(r[3]) : "r"(addr));
}

// packed fp16x2 exp2 via MUFU
__device__ __forceinline__ uint32_t h2exp2_u(uint32_t x) {
    uint32_t r;
    asm("ex2.approx.f16x2 %0, %1;" : "=r"(r) : "r"(x));
    return r;
}

__device__ __forceinline__ uint32_t smem_u32(const void* p) {
    return (uint32_t)__cvta_generic_to_shared(p);
}

// cp.async helpers (16B; invalid -> zero-fill)
__device__ __forceinline__ void cp_async16(void* smem_dst, const void* gsrc, bool valid) {
    unsigned saddr = (unsigned)__cvta_generic_to_shared(smem_dst);
    int sz = valid ? 16 : 0;
    asm volatile("cp.async.cg.shared.global [%0], [%1], 16, %2;\n"
                 :: "r"(saddr), "l"(gsrc), "r"(sz));
}
__device__ __forceinline__ void cp_commit() {
    asm volatile("cp.async.commit_group;\n" ::);
}
template <int N>
__device__ __forceinline__ void cp_wait() {
    asm volatile("cp.async.wait_group %0;\n" :: "n"(N));
}

// ---------------- init: zero txt accumulator + rope inverse-frequency table ----------------
__global__ void init_kernel() {
    int i = blockIdx.x * 256 + threadIdx.x;
    if (i < TXTL * DM) g_txtacc[i] = 0.f;
    if (i < 64) {
        int d0 = 2 * i;
        int dl, da;
        if (d0 < 32)      { dl = d0;      da = 32; }
        else if (d0 < 80) { dl = d0 - 32; da = 48; }
        else              { dl = d0 - 80; da = 48; }
        g_invfreq[i] = powf(10000.0f, -((float)dl) / (float)da);
    }
}

// ---------------- round fp32 -> fp16, elementwise ----------------
__global__ void round_half_kernel(const float* __restrict__ src, __half* __restrict__ dst, int n4) {
    int i = blockIdx.x * 256 + threadIdx.x;
    if (i < n4) {
        float4 v = reinterpret_cast<const float4*>(src)[i];
        reinterpret_cast<__half2*>(dst)[2 * i]     = __floats2half2_rn(v.x, v.y);
        reinterpret_cast<__half2*>(dst)[2 * i + 1] = __floats2half2_rn(v.z, v.w);
    }
}

// ---------------- transpose + round weights: w[K][N] fp32 -> wt[N][K] fp16 ----------------
__global__ void transpose_round_h_kernel(const float* __restrict__ w, __half* __restrict__ wt,
                                         int K, int N) {
    __shared__ float t[32][33];
    int nb = blockIdx.x * 32, kb = blockIdx.y * 32;
    int tx = threadIdx.x, ty = threadIdx.y;   // 32 x 8
#pragma unroll
    for (int j = 0; j < 4; ++j)
        t[ty + j * 8][tx] = w[(long)(kb + ty + j * 8) * N + nb + tx];
    __syncthreads();
#pragma unroll
    for (int j = 0; j < 4; ++j)
        wt[(long)(nb + ty + j * 8) * K + kb + tx] = __float2half_rn(t[tx][ty + j * 8]);
}

// ============= fp16 tensor-core GEMM: C[M,N] = A[M,K] @ Bt[N,K]^T =============
#define GH_STRIDE 40   // halves per row (32 + 8 pad)
#define CS_STRIDE 132
#define GEMM_SMEM_BYTES (128 * CS_STRIDE * 4)   // 67584

template <bool FUSED>
__global__ void __launch_bounds__(256) h16_gemm_t(
    const __half* __restrict__ A, const __half* __restrict__ Bt, float* __restrict__ C,
    int M, int N, int K)
{
    extern __shared__ char smraw[];
    __half* smh = (__half*)smraw;
    float*  cs  = (float*)smraw;

    const int tid  = threadIdx.x;
    const int warp = tid >> 5, lane = tid & 31;
    const int g = lane >> 2, tig = lane & 3;
    const int lr = lane & 15, lk = (lane >> 4) * 8;
    const int wm = (warp & 1) * 64;
    const int wn = (warp >> 1) * 32;
    const int rowBase = blockIdx.y * 128;
    const int colBase = blockIdx.x * 128;
    const int nIter = K / 32;

    float c[4][4][4];
#pragma unroll
    for (int mt = 0; mt < 4; ++mt)
#pragma unroll
        for (int nt = 0; nt < 4; ++nt)
#pragma unroll
            for (int i = 0; i < 4; ++i) c[mt][nt][i] = 0.f;

#pragma unroll
    for (int i = 0; i < 2; ++i) {
        int idx = tid + i * 256;
        int r = idx >> 2, o = idx & 3;
        int grow = rowBase + r;
        cp_async16(&smh[r * GH_STRIDE + o * 8], &A[(long)grow * K + o * 8], grow < M);
        cp_async16(&smh[10240 + r * GH_STRIDE + o * 8], &Bt[(long)(colBase + r) * K + o * 8], true);
    }
    cp_commit();

    for (int it = 0; it < nIter; ++it) {
        int b = it & 1;
        if (it + 1 < nIter) {
            int k0 = (it + 1) * 32;
            int bn = (it + 1) & 1;
#pragma unroll
            for (int i = 0; i < 2; ++i) {
                int idx = tid + i * 256;
                int r = idx >> 2, o = idx & 3;
                int grow = rowBase + r;
                cp_async16(&smh[bn * 5120 + r * GH_STRIDE + o * 8],
                           &A[(long)grow * K + k0 + o * 8], grow < M);
                cp_async16(&smh[10240 + bn * 5120 + r * GH_STRIDE + o * 8],
                           &Bt[(long)(colBase + r) * K + k0 + o * 8], true);
            }
            cp_commit();
            cp_wait<1>();
        } else {
            cp_wait<0>();
        }
        __syncthreads();

        uint32_t aBase = smem_u32(smh) + (b * 5120 + (wm + lr) * GH_STRIDE + lk) * 2;
        uint32_t bBase = smem_u32(smh) + (10240 + b * 5120 + (wn + lr) * GH_STRIDE + lk) * 2;
#pragma unroll
        for (int s = 0; s < 2; ++s) {
            uint32_t af[4][4];
#pragma unroll
            for (int mt = 0; mt < 4; ++mt)
                ldsm_x4(af[mt], aBase + mt * (16 * GH_STRIDE * 2) + s * 32);
#pragma unroll
            for (int np = 0; np < 2; ++np) {
                uint32_t bf[4];
                ldsm_x4(bf, bBase + np * (16 * GH_STRIDE * 2) + s * 32);
#pragma unroll
                for (int mt = 0; mt < 4; ++mt) {
                    mma_f16(c[mt][np * 2],     af[mt], bf[0], bf[2]);
                    mma_f16(c[mt][np * 2 + 1], af[mt], bf[1], bf[3]);
                }
            }
        }
        __syncthreads();
    }

    // stage C tile to fp32 smem
#pragma unroll
    for (int mt = 0; mt < 4; ++mt)
#pragma unroll
        for (int nt = 0; nt < 4; ++nt) {
            int col = wn + nt * 8 + 2 * tig;
            int r0 = wm + mt * 16 + g;
            *reinterpret_cast<float2*>(&cs[r0 * CS_STRIDE + col]) =
                make_float2(c[mt][nt][0], c[mt][nt][1]);
            *reinterpret_cast<float2*>(&cs[(r0 + 8) * CS_STRIDE + col]) =
                make_float2(c[mt][nt][2], c[mt][nt][3]);
        }
    __syncthreads();

    // coalesced write pass
    const int wr = tid >> 4;
    const int c8 = (tid & 15) * 8;
    if (!FUSED) {
#pragma unroll
        for (int j = 0; j < 8; ++j) {
            int r = wr + j * 16;
            int row = rowBase + r;
            if (row >= M) break;
            float4 v0 = *reinterpret_cast<float4*>(&cs[r * CS_STRIDE + c8]);
            float4 v1 = *reinterpret_cast<float4*>(&cs[r * CS_STRIDE + c8 + 4]);
            float4* dst = reinterpret_cast<float4*>(&C[(long)row * N + colBase + c8]);
            dst[0] = v0; dst[1] = v1;
        }
    } else {
        const int section = blockIdx.x >> 2;   // 0=Q,1=K,2=V
        const int head = blockIdx.x & 3;
        float f0 = g_invfreq[(c8 >> 1) + 0], f1 = g_invfreq[(c8 >> 1) + 1];
        float f2 = g_invfreq[(c8 >> 1) + 2], f3 = g_invfreq[(c8 >> 1) + 3];
#pragma unroll
        for (int j = 0; j < 8; ++j) {
            int r = wr + j * 16;
            int token = rowBase + r;
            if (token >= M) break;
            int t = token / 3600, rem = token % 3600;
            int hh = rem / 80, ww2 = rem % 80;
            int it2 = t / 5, tl = t % 5;
            int ih = hh / 9, hl = hh % 9;
            int iw = ww2 >> 4, wl = ww2 & 15;
            int wwin = iw * 10 + ih * 2 + it2;
            int p = tl * 144 + hl * 16 + wl;
            long ob = ((long)(wwin * SEQ + p) * 4 + head) * 128 + c8;
            float4 v0 = *reinterpret_cast<float4*>(&cs[r * CS_STRIDE + c8]);
            float4 v1 = *reinterpret_cast<float4*>(&cs[r * CS_STRIDE + c8 + 4]);
            __half2 o[4];
            if (section == 2) {
                o[0] = __floats2half2_rn(v0.x, v0.y);
                o[1] = __floats2half2_rn(v0.z, v0.w);
                o[2] = __floats2half2_rn(v1.x, v1.y);
                o[3] = __floats2half2_rn(v1.z, v1.w);
                *reinterpret_cast<uint2*>(&g_Vhi_h[ob]) = *reinterpret_cast<uint2*>(&o[0]);
                *reinterpret_cast<uint2*>(&g_Vhi_h[ob + 4]) = *reinterpret_cast<uint2*>(&o[2]);
            } else {
                float pos;
                if (c8 < 32)      pos = (float)t;
                else if (c8 < 80) pos = (float)hh;
                else              pos = (float)ww2;
                float s0 = __sinf(pos * f0), c0 = __cosf(pos * f0);
                float s1 = __sinf(pos * f1), c1 = __cosf(pos * f1);
                float s2 = __sinf(pos * f2), c2 = __cosf(pos * f2);
                float s3 = __sinf(pos * f3), c3 = __cosf(pos * f3);
                o[0] = __floats2half2_rn(v0.x * c0 - v0.y * s0, v0.y * c0 + v0.x * s0);
                o[1] = __floats2half2_rn(v0.z * c1 - v0.w * s1, v0.w * c1 + v0.z * s1);
                o[2] = __floats2half2_rn(v1.x * c2 - v1.y * s2, v1.y * c2 + v1.x * s2);
                o[3] = __floats2half2_rn(v1.z * c3 - v1.w * s3, v1.w * c3 + v1.z * s3);
                __half* base = (section == 0) ? g_Qw_h : g_Kw_h;
                *reinterpret_cast<uint2*>(&base[ob]) = *reinterpret_cast<uint2*>(&o[0]);
                *reinterpret_cast<uint2*>(&base[ob + 4]) = *reinterpret_cast<uint2*>(&o[2]);
            }
        }
    }
}

// ---------------- old tf32 GEMM — small txt GEMMs only ----------------
#define SA_STRIDE 36
#define SB_STRIDE 136
__global__ void __launch_bounds__(256) tf32_gemm_kernel(
    const float* __restrict__ A, const float* __restrict__ B, float* __restrict__ C,
    int M, int N, int K, float alpha)
{
    __shared__ float sA[128 * SA_STRIDE];
    __shared__ float sB[32 * SB_STRIDE];

    const int tid  = threadIdx.x;
    const int warp = tid >> 5, lane = tid & 31;
    const int g = lane >> 2, tig = lane & 3;
    const int wm = (warp & 1) * 64;
    const int wn = (warp >> 1) * 32;
    const int rowBase = blockIdx.y * 128;
    const int colBase = blockIdx.x * 128;

    float c[4][4][4];
#pragma unroll
    for (int mt = 0; mt < 4; ++mt)
#pragma unroll
        for (int nt = 0; nt < 4; ++nt)
#pragma unroll
            for (int i = 0; i < 4; ++i) c[mt][nt][i] = 0.f;

    float4 pa[4], pb[4];
#pragma unroll
    for (int i = 0; i < 4; ++i) {
        int idx = tid + i * 256;
        int r = idx >> 3, c4 = idx & 7;
        int grow = rowBase + r;
        pa[i] = (grow < M) ? *reinterpret_cast<const float4*>(&A[(long)grow * K + c4 * 4])
                           : make_float4(0.f, 0.f, 0.f, 0.f);
        int rb = idx >> 5, cb4 = idx & 31;
        pb[i] = *reinterpret_cast<const float4*>(&B[(long)rb * N + colBase + cb4 * 4]);
    }

    const int nIter = K / 32;
    for (int it = 0; it < nIter; ++it) {
#pragma unroll
        for (int i = 0; i < 4; ++i) {
            int idx = tid + i * 256;
            int r = idx >> 3, c4 = idx & 7;
            float* d = &sA[r * SA_STRIDE + c4 * 4];
            d[0] = to_tf32(pa[i].x); d[1] = to_tf32(pa[i].y);
            d[2] = to_tf32(pa[i].z); d[3] = to_tf32(pa[i].w);
            int rb = idx >> 5, cb4 = idx & 31;
            float* db = &sB[rb * SB_STRIDE + cb4 * 4];
            db[0] = to_tf32(pb[i].x); db[1] = to_tf32(pb[i].y);
            db[2] = to_tf32(pb[i].z); db[3] = to_tf32(pb[i].w);
        }
        __syncthreads();

        if (it + 1 < nIter) {
            int k0 = (it + 1) * 32;
#pragma unroll
            for (int i = 0; i < 4; ++i) {
                int idx = tid + i * 256;
                int r = idx >> 3, c4 = idx & 7;
                int grow = rowBase + r;
                pa[i] = (grow < M) ? *reinterpret_cast<const float4*>(&A[(long)grow * K + k0 + c4 * 4])
                                   : make_float4(0.f, 0.f, 0.f, 0.f);
                int rb = idx >> 5, cb4 = idx & 31;
                pb[i] = *reinterpret_cast<const float4*>(&B[(long)(k0 + rb) * N + colBase + cb4 * 4]);
            }
        }

#pragma unroll
        for (int kk = 0; kk < 4; ++kk) {
            unsigned int af[4][4], bf[4][2];
#pragma unroll
            for (int mt = 0; mt < 4; ++mt) {
                int r0 = wm + mt * 16 + g;
                af[mt][0] = __float_as_uint(sA[r0 * SA_STRIDE + kk * 8 + tig]);
                af[mt][1] = __float_as_uint(sA[(r0 + 8) * SA_STRIDE + kk * 8 + tig]);
                af[mt][2] = __float_as_uint(sA[r0 * SA_STRIDE + kk * 8 + tig + 4]);
                af[mt][3] = __float_as_uint(sA[(r0 + 8) * SA_STRIDE + kk * 8 + tig + 4]);
            }
#pragma unroll
            for (int nt = 0; nt < 4; ++nt) {
                int cn = wn + nt * 8 + g;
                bf[nt][0] = __float_as_uint(sB[(kk * 8 + tig) * SB_STRIDE + cn]);
                bf[nt][1] = __float_as_uint(sB[(kk * 8 + tig + 4) * SB_STRIDE + cn]);
            }
#pragma unroll
            for (int mt = 0; mt < 4; ++mt)
#pragma unroll
                for (int nt = 0; nt < 4; ++nt)
                    mma_tf32(c[mt][nt], af[mt][0], af[mt][1], af[mt][2], af[mt][3],
                             bf[nt][0], bf[nt][1]);
        }
        __syncthreads();
    }

#pragma unroll
    for (int mt = 0; mt < 4; ++mt) {
#pragma unroll
        for (int nt = 0; nt < 4; ++nt) {
            int row0 = rowBase + wm + mt * 16 + g;
            int col = colBase + wn + nt * 8 + 2 * tig;
            if (row0 < M) {
                float2 o = make_float2(c[mt][nt][0] * alpha, c[mt][nt][1] * alpha);
                *reinterpret_cast<float2*>(&C[(long)row0 * N + col]) = o;
            }
            int row1 = row0 + 8;
            if (row1 < M) {
                float2 o = make_float2(c[mt][nt][2] * alpha, c[mt][nt][3] * alpha);
                *reinterpret_cast<float2*>(&C[(long)row1 * N + col]) = o;
            }
        }
    }
}

// ---------------- broadcast txt qkv rows into all windows (no rope) ----------------
__global__ void __launch_bounds__(256) txt_broadcast_kernel() {
    int w = blockIdx.x, tr = blockIdx.y;
    int tid = threadIdx.x;
    int h = tid >> 6, pr = tid & 63;
    int d0 = pr * 2;
    const float* base = &g_qkv_t[(long)tr * 1536 + h * 128];
    float q0 = base[d0],        q1 = base[d0 + 1];
    float k0 = base[512 + d0],  k1 = base[512 + d0 + 1];
    float v0 = base[1024 + d0], v1 = base[1024 + d0 + 1];
    long ob = ((long)(w * SEQ + WS + tr) * 4 + h) * 128 + d0;
    *reinterpret_cast<__half2*>(&g_Qw_h[ob])  = __floats2half2_rn(q0, q1);
    *reinterpret_cast<__half2*>(&g_Kw_h[ob])  = __floats2half2_rn(k0, k1);
    *reinterpret_cast<__half2*>(&g_Vhi_h[ob]) = __floats2half2_rn(v0, v1);
}

// ---------------- fp16 flash attention: QT=128, KT=64; kt-peel + compile-time q-tail ----
#define QT2   128
#define KT2   64
#define PADDH 136
#define PSTR  72
#define NKT   13
#define SMEM_K0   17408
#define SMEM_KBUF 9216
#define SMEM_V    35840
#define ATTN3_SMEM_BYTES 90112

// TAIL=false: qtiles 0..5 (all 128 q-rows valid). TAIL=true: qt==6, rows 768..783 valid
// (all txt rows); only warps with wm==0 compute, mt=0 only.
template <bool TAIL>
__global__ void __launch_bounds__(256) attn3_t() {
    extern __shared__ char smraw[];
    __half* sh = (__half*)smraw;
    float* sPart = (float*)(smraw + 89088);
    const uint32_t sbase = smem_u32(sh);

    const float NEGINF = __int_as_float(0xff800000);
    const float scale = 0.08838834764831843f;
    const float SL = 0.12751089f;
    const uint32_t ONES2 = 0x3C003C00u;
    constexpr int MT = TAIL ? 1 : 2;

    int qt = TAIL ? 6 : blockIdx.x;
    int h = blockIdx.y, w = blockIdx.z;
    int tid = threadIdx.x;
    const int warp = tid >> 5, lane = tid & 31;
    const int g = lane >> 2, tig = lane & 3;
    const int lr = lane & 15, lk = (lane >> 4) * 8;
    const int wm = (warp & 3) * 32;
    const int ng = warp >> 2;
    const int wn1 = ng * 32;
    const int wn2 = ng * 64;
    const bool wActive = TAIL ? (wm == 0) : true;   // warp-uniform

    const long gbase = ((long)(w * SEQ) * 4 + h) * 128;
    const int qrow0 = qt * QT2;

    // prologue: Q + K0, one commit group
#pragma unroll
    for (int i = 0; i < 8; ++i) {
        int idx = tid + i * 256;
        int r = idx >> 4, o = idx & 15;
        cp_async16(&sh[r * PADDH + o * 8],
                   &g_Qw_h[gbase + (long)(qrow0 + r) * 512 + o * 8], qrow0 + r < SEQ);
    }
#pragma unroll
    for (int i = 0; i < 4; ++i) {
        int idx = tid + i * 256;
        int r = idx >> 4, o = idx & 15;
        cp_async16(&sh[SMEM_K0 + r * PADDH + o * 8],
                   &g_Kw_h[gbase + (long)r * 512 + o * 8], r < SEQ);
    }
    cp_commit();

    float oacc[2][8][4];
#pragma unroll
    for (int mt = 0; mt < MT; ++mt)
#pragma unroll
        for (int nf = 0; nf < 8; ++nf)
#pragma unroll
            for (int i = 0; i < 4; ++i) oacc[mt][nf][i] = 0.f;

    float lex[2][4];
#pragma unroll
    for (int mt = 0; mt < MT; ++mt)
#pragma unroll
        for (int i = 0; i < 4; ++i) lex[mt][i] = 0.f;

    float mOld[2][2];
#pragma unroll
    for (int mt = 0; mt < MT; ++mt)
#pragma unroll
        for (int hf = 0; hf < 2; ++hf) mOld[mt][hf] = NEGINF;

    // ================= main loop: kt = 0..11 =================
    for (int kt = 0; kt < NKT - 1; ++kt) {
        const int b = kt & 1;
        const int kbase = kt * KT2;
        __half* sKb = sh + SMEM_K0 + b * SMEM_KBUF;
        __half* sP  = sKb;

        __syncthreads();

        {
#pragma unroll
            for (int i = 0; i < 4; ++i) {
                int idx = tid + i * 256;
                int r = idx >> 4, o = idx & 15;
                cp_async16(&sh[SMEM_V + r * PADDH + o * 8],
                           &g_Vhi_h[gbase + (long)(kbase + r) * 512 + o * 8], kbase + r < SEQ);
            }
            cp_commit();
        }
        {
            int kb = kbase + KT2;
            __half* sKn = sh + SMEM_K0 + ((kt + 1) & 1) * SMEM_KBUF;
#pragma unroll
            for (int i = 0; i < 4; ++i) {
                int idx = tid + i * 256;
                int r = idx >> 4, o = idx & 15;
                cp_async16(&sKn[r * PADDH + o * 8],
                           &g_Kw_h[gbase + (long)(kb + r) * 512 + o * 8], kb + r < SEQ);
            }
            cp_commit();
            cp_wait<2>();
        }
        __syncthreads();

        float aF[2][2];
        if (wActive) {
            // ---- phase 1: S = Q @ K^T ----
            float sacc[2][4][4];
#pragma unroll
            for (int mt = 0; mt < MT; ++mt)
#pragma unroll
                for (int nf = 0; nf < 4; ++nf)
#pragma unroll
                    for (int i = 0; i < 4; ++i) sacc[mt][nf][i] = 0.f;

            {
                uint32_t qa0 = sbase + ((wm + lr) * PADDH + lk) * 2;
                uint32_t ka0 = smem_u32(sKb) + ((wn1 + lr) * PADDH + lk) * 2;
#pragma unroll
                for (int kk = 0; kk < 8; ++kk) {
                    uint32_t aQ[2][4];
#pragma unroll
                    for (int mt = 0; mt < MT; ++mt)
                        ldsm_x4(aQ[mt], qa0 + mt * (16 * PADDH * 2) + kk * 32);
#pragma unroll
                    for (int np = 0; np < 2; ++np) {
                        uint32_t bK[4];
                        ldsm_x4(bK, ka0 + np * (16 * PADDH * 2) + kk * 32);
#pragma unroll
                        for (int mt = 0; mt < MT; ++mt) {
                            mma_f16(sacc[mt][np * 2],     aQ[mt], bK[0], bK[2]);
                            mma_f16(sacc[mt][np * 2 + 1], aQ[mt], bK[1], bK[3]);
                        }
                    }
                }
            }

            // ---- row max (all K cols valid for kt < 12) ----
#pragma unroll
            for (int mt = 0; mt < MT; ++mt)
#pragma unroll
                for (int hf = 0; hf < 2; ++hf) {
                    float m = NEGINF;
#pragma unroll
                    for (int nf = 0; nf < 4; ++nf)
#pragma unroll
                        for (int pr = 0; pr < 2; ++pr)
                            m = fmaxf(m, sacc[mt][nf][hf * 2 + pr]);
                    m = fmaxf(m, __shfl_xor_sync(0xffffffffu, m, 1));
                    m = fmaxf(m, __shfl_xor_sync(0xffffffffu, m, 2));
                    if (tig == 0)
                        sPart[(wm + mt * 16 + g + hf * 8) * 2 + ng] = m;
                }
            __syncthreads();

            // ---- exp2.f16x2 + P(half) write ----
#pragma unroll
            for (int mt = 0; mt < MT; ++mt)
#pragma unroll
                for (int hf = 0; hf < 2; ++hf) {
                    int row = wm + mt * 16 + g + hf * 8;
                    float mn = fmaxf(mOld[mt][hf], fmaxf(sPart[row * 2], sPart[row * 2 + 1]));
                    aF[mt][hf] = __expf((mOld[mt][hf] - mn) * scale);
                    mOld[mt][hf] = mn;
                }
#pragma unroll
            for (int mt = 0; mt < MT; ++mt)
#pragma unroll
                for (int hf = 0; hf < 2; ++hf) {
                    int row = wm + mt * 16 + g + hf * 8;
                    float mnSL = mOld[mt][hf] * SL;
#pragma unroll
                    for (int nf = 0; nf < 4; ++nf) {
                        float a0 = fmaf(sacc[mt][nf][hf * 2],     SL, -mnSL);
                        float a1 = fmaf(sacc[mt][nf][hf * 2 + 1], SL, -mnSL);
                        __half2 ha = __floats2half2_rn(a0, a1);
                        uint32_t p2 = h2exp2_u(*reinterpret_cast<uint32_t*>(&ha));
                        int col = wn1 + nf * 8 + 2 * tig;
                        *reinterpret_cast<uint32_t*>(&sP[row * PSTR + col]) = p2;
                    }
                }
        } else {
            __syncthreads();   // match wActive path's barrier
        }
        cp_wait<1>();
        __syncthreads();

        if (wActive) {
            // ---- rescale O and l ----
#pragma unroll
            for (int mt = 0; mt < MT; ++mt) {
#pragma unroll
                for (int nf = 0; nf < 8; ++nf) {
                    oacc[mt][nf][0] *= aF[mt][0]; oacc[mt][nf][1] *= aF[mt][0];
                    oacc[mt][nf][2] *= aF[mt][1]; oacc[mt][nf][3] *= aF[mt][1];
                }
                lex[mt][0] *= aF[mt][0]; lex[mt][1] *= aF[mt][0];
                lex[mt][2] *= aF[mt][1]; lex[mt][3] *= aF[mt][1];
            }

            // ---- phase 2: O += P @ V (+ l += P @ ones) ----
            uint32_t pa0 = smem_u32(sP) + ((wm + lr) * PSTR + lk) * 2;
            int vkr = ((lane >> 3) & 1) * 8 + (lane & 7);
            int vnc = (lane >> 4) * 8;
            uint32_t va0 = sbase + (SMEM_V + vkr * PADDH + wn2 + vnc) * 2;
#pragma unroll
            for (int kk2 = 0; kk2 < 4; ++kk2) {
                uint32_t aP[2][4];
#pragma unroll
                for (int mt = 0; mt < MT; ++mt) {
                    ldsm_x4(aP[mt], pa0 + mt * (16 * PSTR * 2) + kk2 * 32);
                    mma_f16(lex[mt], aP[mt], ONES2, ONES2);
                }
#pragma unroll
                for (int ng2 = 0; ng2 < 4; ++ng2) {
                    uint32_t bh[4];
                    ldsm_x4_t(bh, va0 + kk2 * (16 * PADDH * 2) + ng2 * 32);
#pragma unroll
                    for (int mt = 0; mt < MT; ++mt) {
                        mma_f16(oacc[mt][ng2 * 2],     aP[mt], bh[0], bh[1]);
                        mma_f16(oacc[mt][ng2 * 2 + 1], aP[mt], bh[2], bh[3]);
                    }
                }
            }
        }
    }

    // ================= peeled kt = 12 (kbase=768; 16 valid cols) =================
    {
        __half* sKb = sh + SMEM_K0;      // (12 & 1) == 0
        __half* sP  = sKb;

        __syncthreads();
#pragma unroll
        for (int i = 0; i < 4; ++i) {
            int idx = tid + i * 256;
            int r = idx >> 4, o = idx & 15;
            cp_async16(&sh[SMEM_V + r * PADDH + o * 8],
                       &g_Vhi_h[gbase + (long)(768 + r) * 512 + o * 8], 768 + r < SEQ);
        }
        cp_commit();
        cp_wait<1>();    // K[12] complete
        __syncthreads();

        float sacc[2][2][4];   // np=0 only: cols 768..783, ALL valid
        if (wActive && ng == 0) {
#pragma unroll
            for (int mt = 0; mt < MT; ++mt)
#pragma unroll
                for (int nf = 0; nf < 2; ++nf)
#pragma unroll
                    for (int i = 0; i < 4; ++i) sacc[mt][nf][i] = 0.f;
            uint32_t qa0 = sbase + ((wm + lr) * PADDH + lk) * 2;
            uint32_t ka0 = smem_u32(sKb) + (lr * PADDH + lk) * 2;
#pragma unroll
            for (int kk = 0; kk < 8; ++kk) {
                uint32_t aQ[2][4];
#pragma unroll
                for (int mt = 0; mt < MT; ++mt)
                    ldsm_x4(aQ[mt], qa0 + mt * (16 * PADDH * 2) + kk * 32);
                uint32_t bK[4];
                ldsm_x4(bK, ka0 + kk * 32);
#pragma unroll
                for (int mt = 0; mt < MT; ++mt) {
                    mma_f16(sacc[mt][0], aQ[mt], bK[0], bK[2]);
                    mma_f16(sacc[mt][1], aQ[mt], bK[1], bK[3]);
                }
            }
#pragma unroll
            for (int mt = 0; mt < MT; ++mt)
#pragma unroll
                for (int hf = 0; hf < 2; ++hf) {
                    float m = fmaxf(fmaxf(sacc[mt][0][hf * 2], sacc[mt][0][hf * 2 + 1]),
                                    fmaxf(sacc[mt][1][hf * 2], sacc[mt][1][hf * 2 + 1]));
                    m = fmaxf(m, __shfl_xor_sync(0xffffffffu, m, 1));
                    m = fmaxf(m, __shfl_xor_sync(0xffffffffu, m, 2));
                    if (tig == 0)
                        sPart[(wm + mt * 16 + g + hf * 8) * 2] = m;
                }
        } else if (wActive) {   // ng == 1
            if (tig == 0) {
#pragma unroll
                for (int mt = 0; mt < MT; ++mt)
#pragma unroll
                    for (int hf = 0; hf < 2; ++hf)
                        sPart[(wm + mt * 16 + g + hf * 8) * 2 + 1] = NEGINF;
            }
        }
        __syncthreads();

        float aF[2][2];
        if (wActive) {
#pragma unroll
            for (int mt = 0; mt < MT; ++mt)
#pragma unroll
                for (int hf = 0; hf < 2; ++hf) {
                    int row = wm + mt * 16 + g + hf * 8;
                    float mn = fmaxf(mOld[mt][hf], fmaxf(sPart[row * 2], sPart[row * 2 + 1]));
                    aF[mt][hf] = __expf((mOld[mt][hf] - mn) * scale);
                    mOld[mt][hf] = mn;
                }
            if (ng == 0) {
#pragma unroll
                for (int mt = 0; mt < MT; ++mt)
#pragma unroll
                    for (int hf = 0; hf < 2; ++hf) {
                        int row = wm + mt * 16 + g + hf * 8;
                        float mnSL = mOld[mt][hf] * SL;
#pragma unroll
                        for (int nf = 0; nf < 2; ++nf) {
                            float a0 = fmaf(sacc[mt][nf][hf * 2],     SL, -mnSL);
                            float a1 = fmaf(sacc[mt][nf][hf * 2 + 1], SL, -mnSL);
                            __half2 ha = __floats2half2_rn(a0, a1);
                            uint32_t p2 = h2exp2_u(*reinterpret_cast<uint32_t*>(&ha));
                            int col = nf * 8 + 2 * tig;
                            *reinterpret_cast<uint32_t*>(&sP[row * PSTR + col]) = p2;
                        }
                    }
            }
        }
        cp_wait<0>();
        __syncthreads();

        if (wActive) {
#pragma unroll
            for (int mt = 0; mt < MT; ++mt) {
#pragma unroll
                for (int nf = 0; nf < 8; ++nf) {
                    oacc[mt][nf][0] *= aF[mt][0]; oacc[mt][nf][1] *= aF[mt][0];
                    oacc[mt][nf][2] *= aF[mt][1]; oacc[mt][nf][3] *= aF[mt][1];
                }
                lex[mt][0] *= aF[mt][0]; lex[mt][1] *= aF[mt][0];
                lex[mt][2] *= aF[mt][1]; lex[mt][3] *= aF[mt][1];
            }

            // phase 2: kk2 = 0 only (P cols 16..63 exactly zero)
            uint32_t pa0 = smem_u32(sP) + ((wm + lr) * PSTR + lk) * 2;
            int vkr = ((lane >> 3) & 1) * 8 + (lane & 7);
            int vnc = (lane >> 4) * 8;
            uint32_t va0 = sbase + (SMEM_V + vkr * PADDH + wn2 + vnc) * 2;
            uint32_t aP[2][4];
#pragma unroll
            for (int mt = 0; mt < MT; ++mt) {
                ldsm_x4(aP[mt], pa0 + mt * (16 * PSTR * 2));
                mma_f16(lex[mt], aP[mt], ONES2, ONES2);
            }
#pragma unroll
            for (int ng2 = 0; ng2 < 4; ++ng2) {
                uint32_t bh[4];
                ldsm_x4_t(bh, va0 + ng2 * 32);
#pragma unroll
                for (int mt = 0; mt < MT; ++mt) {
                    mma_f16(oacc[mt][ng2 * 2],     aP[mt], bh[0], bh[1]);
                    mma_f16(oacc[mt][ng2 * 2 + 1], aP[mt], bh[2], bh[3]);
                }
            }
        }
    }

    // epilogue
    if (wActive) {
#pragma unroll
        for (int mt = 0; mt < MT; ++mt)
#pragma unroll
            for (int hf = 0; hf < 2; ++hf) {
                int ql = wm + mt * 16 + g + hf * 8;
                int qg = qrow0 + ql;
                if (qg >= SEQ) continue;
                float inv = 1.f / lex[mt][hf * 2];
                if (qg >= WS) {
                    int tr = qg - WS;
                    float* dst = &g_txtacc[(long)tr * DM + h * 128];
#pragma unroll
                    for (int nf = 0; nf < 8; ++nf) {
                        int col = wn2 + nf * 8 + 2 * tig;
                        atomicAdd(&dst[col],     oacc[mt][nf][hf * 2] * inv);
                        atomicAdd(&dst[col + 1], oacc[mt][nf][hf * 2 + 1] * inv);
                    }
                } else {
#pragma unroll
                    for (int nf = 0; nf < 8; ++nf) {
                        int col = wn2 + nf * 8 + 2 * tig;
                        *reinterpret_cast<__half2*>(&sh[ql * PADDH + col]) =
                            __floats2half2_rn(oacc[mt][nf][hf * 2] * inv,
                                              oacc[mt][nf][hf * 2 + 1] * inv);
                    }
                }
            }
    }
    __syncthreads();

    // coalesced scatter: vid rows only (TAIL has none; loop exits immediately)
    {
        int wr = tid >> 4, c8 = (tid & 15) * 8;
#pragma unroll
        for (int j = 0; j < 8; ++j) {
            int ql = wr + j * 16;
            int qg = qrow0 + ql;
            if (qg >= WS) break;
            int token = token_of(w, qg);
            uint4 v = *reinterpret_cast<uint4*>(&sh[ql * PADDH + c8]);
            *reinterpret_cast<uint4*>(&g_preproj_h[(long)token * DM + h * 128 + c8]) = v;
        }
    }
}

// ---------------- launch ----------------
extern "C" void kernel_launch(void* const* d_in, const int* in_sizes, int n_in,
                              void* d_out, int out_size) {
    const float* vid       = (const float*)d_in[0];
    const float* txt       = (const float*)d_in[1];
    const float* w_qkv_vid = (const float*)d_in[2];
    const float* w_qkv_txt = (const float*)d_in[3];
    const float* w_out_vid = (const float*)d_in[4];
    const float* w_out_txt = (const float*)d_in[5];
    float* out = (float*)d_out;

    cudaFuncSetAttribute(attn3_t<false>, cudaFuncAttributeMaxDynamicSharedMemorySize,
                         ATTN3_SMEM_BYTES);
    cudaFuncSetAttribute(attn3_t<true>, cudaFuncAttributeMaxDynamicSharedMemorySize,
                         ATTN3_SMEM_BYTES);
    cudaFuncSetAttribute(h16_gemm_t<true>, cudaFuncAttributeMaxDynamicSharedMemorySize,
                         GEMM_SMEM_BYTES);
    cudaFuncSetAttribute(h16_gemm_t<false>, cudaFuncAttributeMaxDynamicSharedMemorySize,
                         GEMM_SMEM_BYTES);

    float *p_qkv_t, *p_txt;
    __half *p_pre_h, *p_vid_h, *p_wqkvT_h, *p_woutT_h;
    cudaGetSymbolAddress((void**)&p_qkv_t,   g_qkv_t);
    cudaGetSymbolAddress((void**)&p_txt,     g_txtacc);
    cudaGetSymbolAddress((void**)&p_pre_h,   g_preproj_h);
    cudaGetSymbolAddress((void**)&p_vid_h,   g_vid_h);
    cudaGetSymbolAddress((void**)&p_wqkvT_h, g_wqkvT_h);
    cudaGetSymbolAddress((void**)&p_woutT_h, g_woutT_h);

    init_kernel<<<(TXTL * DM + 255) / 256, 256>>>();

    // fp16 conversions
    round_half_kernel<<<(N_VID * DM / 4 + 255) / 256, 256>>>(vid, p_vid_h, N_VID * DM / 4);
    transpose_round_h_kernel<<<dim3(1536 / 32, DM / 32), dim3(32, 8)>>>(w_qkv_vid, p_wqkvT_h, DM, 1536);
    transpose_round_h_kernel<<<dim3(DM / 32, DM / 32), dim3(32, 8)>>>(w_out_vid, p_woutT_h, DM, DM);

    // txt QKV (fp32), then broadcast into windows
    tf32_gemm_kernel<<<dim3(1536 / 128, 1), 256>>>(
        txt, w_qkv_txt, p_qkv_t, TXTL, 1536, DM, 1.f);

    // vid QKV projection with fused rope + window scatter (coalesced)
    h16_gemm_t<true><<<dim3(1536 / 128, (N_VID + 127) / 128), 256, GEMM_SMEM_BYTES>>>(
        p_vid_h, p_wqkvT_h, (float*)nullptr, N_VID, 1536, DM);

    txt_broadcast_kernel<<<dim3(NWIN, TXTL), 256>>>();

    // attention: full tiles + specialized q-tail
    attn3_t<false><<<dim3(6, 4, NWIN), 256, ATTN3_SMEM_BYTES>>>();
    attn3_t<true><<<dim3(1, 4, NWIN), 256, ATTN3_SMEM_BYTES>>>();

    // output projections
    h16_gemm_t<false><<<dim3(DM / 128, (N_VID + 127) / 128), 256, GEMM_SMEM_BYTES>>>(
        p_pre_h, p_woutT_h, out, N_VID, DM, DM);
    tf32_gemm_kernel<<<dim3(DM / 128, 1), 256>>>(
        p_txt, w_out_txt, out + (long)N_VID * DM, TXTL, DM, DM, 1.f / 50.f);
}